// round 12
// baseline (speedup 1.0000x reference)
#include <cuda_runtime.h>
#include <cuda_bf16.h>
#include <cuda_fp16.h>
#include <cstdint>
#include <cstddef>

#define BATCH  2
#define SEQ    2048
#define DMODEL 1024
#define NHEAD  16
#define DK     64
#define MROWS  (BATCH * SEQ)
#define KDIM   1024

typedef __nv_bfloat16 bf16;

__device__ __half g_q[BATCH * NHEAD * SEQ * DK];
__device__ __half g_k[BATCH * NHEAD * SEQ * DK];
__device__ __half g_v[BATCH * NHEAD * DK * SEQ];
__device__ bf16  g_xh[MROWS * DMODEL];
__device__ bf16  g_xl[MROWS * DMODEL];
__device__ bf16  g_aoh[MROWS * DMODEL];
__device__ bf16  g_aol[MROWS * DMODEL];
__device__ bf16  g_wqh[DMODEL * DMODEL];
__device__ bf16  g_wql[DMODEL * DMODEL];
__device__ bf16  g_wkh[DMODEL * DMODEL];
__device__ bf16  g_wkl[DMODEL * DMODEL];
__device__ bf16  g_wvh[DMODEL * DMODEL];
__device__ bf16  g_wvl[DMODEL * DMODEL];
__device__ bf16  g_woh[DMODEL * DMODEL];
__device__ bf16  g_wol[DMODEL * DMODEL];

__device__ __forceinline__ uint32_t smem_u32(const void* p) {
    uint32_t a;
    asm("{ .reg .u64 t; cvta.to.shared.u64 t, %1; cvt.u32.u64 %0, t; }"
        : "=r"(a) : "l"(p));
    return a;
}

#define CP_ASYNC16(dst_u32, src_ptr) \
    asm volatile("cp.async.cg.shared.global [%0], [%1], 16;" \
        :: "r"(dst_u32), "l"((const void*)(src_ptr)) : "memory")
#define CP_COMMIT() asm volatile("cp.async.commit_group;" ::: "memory")
#define CP_WAIT(n)  asm volatile("cp.async.wait_group %0;" :: "n"(n) : "memory")

#define LDSM_X4(r0, r1, r2, r3, addr) \
    asm volatile("ldmatrix.sync.aligned.m8n8.x4.shared.b16 {%0,%1,%2,%3}, [%4];" \
        : "=r"(r0), "=r"(r1), "=r"(r2), "=r"(r3) : "r"(addr))

__device__ __forceinline__ void mma_bf16(float c[4], uint32_t a0, uint32_t a1,
                                         uint32_t a2, uint32_t a3,
                                         uint32_t b0, uint32_t b1) {
    asm volatile(
        "mma.sync.aligned.m16n8k16.row.col.f32.bf16.bf16.f32 "
        "{%0,%1,%2,%3}, {%4,%5,%6,%7}, {%8,%9}, {%0,%1,%2,%3};"
        : "+f"(c[0]), "+f"(c[1]), "+f"(c[2]), "+f"(c[3])
        : "r"(a0), "r"(a1), "r"(a2), "r"(a3), "r"(b0), "r"(b1));
}

__device__ __forceinline__ void mma_f16(float c[4], uint32_t a0, uint32_t a1,
                                        uint32_t a2, uint32_t a3,
                                        uint32_t b0, uint32_t b1) {
    asm volatile(
        "mma.sync.aligned.m16n8k16.row.col.f32.f16.f16.f32 "
        "{%0,%1,%2,%3}, {%4,%5,%6,%7}, {%8,%9}, {%0,%1,%2,%3};"
        : "+f"(c[0]), "+f"(c[1]), "+f"(c[2]), "+f"(c[3])
        : "r"(a0), "r"(a1), "r"(a2), "r"(a3), "r"(b0), "r"(b1));
}

__device__ __forceinline__ void bf16_split(float v, bf16& h, bf16& l) {
    h = __float2bfloat16_rn(v);
    l = __float2bfloat16_rn(v - __bfloat162float(h));
}

// ---------------- fused hi/lo bf16 split pre-pass ----------------
#define NX4 ((MROWS * DMODEL) / 4)
#define NW4 ((DMODEL * DMODEL) / 4)
#define NTASK (NX4 + 4 * NW4)

__global__ void split_all_kernel(
    const float* __restrict__ x,
    const float* __restrict__ Wq, const float* __restrict__ Wk,
    const float* __restrict__ Wv, const float* __restrict__ Wo,
    bf16* __restrict__ xh, bf16* __restrict__ xl,
    bf16* __restrict__ wqh, bf16* __restrict__ wql,
    bf16* __restrict__ wkh, bf16* __restrict__ wkl,
    bf16* __restrict__ wvh, bf16* __restrict__ wvl,
    bf16* __restrict__ woh, bf16* __restrict__ wol)
{
    int i = blockIdx.x * blockDim.x + threadIdx.x;
    if (i >= NTASK) return;
    const float* in;
    bf16 *oh, *ol;
    int o;
    if (i < NX4) {
        in = x; oh = xh; ol = xl; o = i;
    } else {
        int j = i - NX4;
        int t = j / NW4;
        o = j - t * NW4;
        in = (t == 0) ? Wq : (t == 1) ? Wk : (t == 2) ? Wv : Wo;
        oh = (t == 0) ? wqh : (t == 1) ? wkh : (t == 2) ? wvh : woh;
        ol = (t == 0) ? wql : (t == 1) ? wkl : (t == 2) ? wvl : wol;
    }
    float4 v = ((const float4*)in)[o];
    __nv_bfloat162 h0, h1, l0, l1;
    bf16 h, l;
    bf16_split(v.x, h, l); h0.x = h; l0.x = l;
    bf16_split(v.y, h, l); h0.y = h; l0.y = l;
    bf16_split(v.z, h, l); h1.x = h; l1.x = l;
    bf16_split(v.w, h, l); h1.y = h; l1.y = l;
    ((__nv_bfloat162*)oh)[2 * o + 0] = h0;
    ((__nv_bfloat162*)oh)[2 * o + 1] = h1;
    ((__nv_bfloat162*)ol)[2 * o + 0] = l0;
    ((__nv_bfloat162*)ol)[2 * o + 1] = l1;
}

// ---------------- 3xBF16 GEMM (ldmatrix, dependency-spaced mma) -------------
// modes: 0 fp32 row-major+bias; 1 Q fp16 [B,H,s,d]*0.125; 2 K fp16 [B,H,s,d];
//        3 V fp16 [B,H,d,s]
#define BBK 32
#define BRS 40
#define B_TILE (128 * BRS)
#define B_STAGE (4 * B_TILE)
#define B_SMEM (2 * B_STAGE * 2)

__device__ __forceinline__ void gemmb_load(
    const bf16* __restrict__ Ah, const bf16* __restrict__ Al,
    const bf16* __restrict__ Wh, const bf16* __restrict__ Wl,
    int bm, int bn, uint32_t base, int tid, int k0, int s)
{
    const bf16* bases[4] = {
        Ah + (size_t)bm * KDIM, Al + (size_t)bm * KDIM,
        Wh + (size_t)bn * KDIM, Wl + (size_t)bn * KDIM };
    const uint32_t st = base + (uint32_t)(s * B_STAGE) * 2;
#pragma unroll
    for (int i = 0; i < 8; i++) {
        const int task = tid + 256 * i;
        const int t = task >> 9;
        const int rem = task & 511;
        const int r = rem >> 2;
        const int seg = rem & 3;
        const bf16* src = bases[t] + (size_t)r * KDIM + k0 + seg * 8;
        const uint32_t dst = st + (uint32_t)(t * B_TILE + r * BRS + seg * 8) * 2;
        CP_ASYNC16(dst, src);
    }
}

__global__ void __launch_bounds__(256, 2) gemm3_bf16(
    const bf16* __restrict__ Ah, const bf16* __restrict__ Al,
    const bf16* __restrict__ Wh0, const bf16* __restrict__ Wl0,
    const float* __restrict__ b0v, void* __restrict__ C0,
    const bf16* __restrict__ Wh1, const bf16* __restrict__ Wl1,
    const float* __restrict__ b1v, void* __restrict__ C1,
    const bf16* __restrict__ Wh2, const bf16* __restrict__ Wl2,
    const float* __restrict__ b2v, void* __restrict__ C2,
    int m0, int m1, int m2)
{
    extern __shared__ char smem_raw[];
    const uint32_t base = smem_u32(smem_raw);
    const int tid = threadIdx.x;
    const int wid = tid >> 5;
    const int lane = tid & 31;
    const int G = lane >> 2;
    const int T = lane & 3;
    const int wm = (wid >> 2) * 64;
    const int wn = (wid & 3) * 32;
    const int bm = blockIdx.y * 128;
    const int bn = blockIdx.x * 128;
    const int z = blockIdx.z;

    const bf16* Wh = (z == 0) ? Wh0 : (z == 1) ? Wh1 : Wh2;
    const bf16* Wl = (z == 0) ? Wl0 : (z == 1) ? Wl1 : Wl2;
    const float* bias = (z == 0) ? b0v : (z == 1) ? b1v : b2v;
    void* C = (z == 0) ? C0 : (z == 1) ? C1 : C2;
    const int mode = (z == 0) ? m0 : (z == 1) ? m1 : m2;

    const int a_r = lane & 15;
    const int a_c = (lane & 16) ? 8 : 0;
    const int b_r = (lane & 7) + ((lane & 16) ? 8 : 0);
    const int b_c = (lane & 8) ? 8 : 0;
    const uint32_t a_addr0 = base + (uint32_t)((wm + a_r) * BRS + a_c) * 2;
    const uint32_t b_addr0 = base + (uint32_t)((wn + b_r) * BRS + b_c) * 2
                           + (uint32_t)(2 * B_TILE) * 2;

    float c[4][4][4];
#pragma unroll
    for (int mt = 0; mt < 4; mt++)
#pragma unroll
        for (int nt = 0; nt < 4; nt++)
#pragma unroll
            for (int i = 0; i < 4; i++) c[mt][nt][i] = 0.0f;

    gemmb_load(Ah, Al, Wh, Wl, bm, bn, base, tid, 0, 0);
    CP_COMMIT();

    const int NIT = KDIM / BBK;
    for (int k = 0; k < NIT; k++) {
        if (k + 1 < NIT) {
            gemmb_load(Ah, Al, Wh, Wl, bm, bn, base, tid, (k + 1) * BBK, (k + 1) & 1);
            CP_COMMIT();
            CP_WAIT(1);
        } else {
            CP_WAIT(0);
        }
        __syncthreads();

        const uint32_t sb = (uint32_t)((k & 1) * B_STAGE) * 2;
        const uint32_t tile2 = (uint32_t)B_TILE * 2;

#pragma unroll
        for (int ko = 0; ko < BBK; ko += 16) {
            uint32_t bh_[4][2], bl_[4][2];
#pragma unroll
            for (int ntp = 0; ntp < 2; ntp++) {
                const uint32_t ba = b_addr0 + sb + (uint32_t)(ntp * 16 * BRS + ko) * 2;
                LDSM_X4(bh_[2 * ntp][0], bh_[2 * ntp][1],
                        bh_[2 * ntp + 1][0], bh_[2 * ntp + 1][1], ba);
                LDSM_X4(bl_[2 * ntp][0], bl_[2 * ntp][1],
                        bl_[2 * ntp + 1][0], bl_[2 * ntp + 1][1], ba + tile2);
            }
#pragma unroll
            for (int mt = 0; mt < 4; mt++) {
                const uint32_t aa = a_addr0 + sb + (uint32_t)(mt * 16 * BRS + ko) * 2;
                uint32_t ah0, ah1, ah2, ah3, al0, al1, al2, al3;
                LDSM_X4(ah0, ah1, ah2, ah3, aa);
                LDSM_X4(al0, al1, al2, al3, aa + tile2);
                // term passes: same-accumulator reuse distance = 4
#pragma unroll
                for (int nt = 0; nt < 4; nt++)
                    mma_bf16(c[mt][nt], ah0, ah1, ah2, ah3, bh_[nt][0], bh_[nt][1]);
#pragma unroll
                for (int nt = 0; nt < 4; nt++)
                    mma_bf16(c[mt][nt], al0, al1, al2, al3, bh_[nt][0], bh_[nt][1]);
#pragma unroll
                for (int nt = 0; nt < 4; nt++)
                    mma_bf16(c[mt][nt], ah0, ah1, ah2, ah3, bl_[nt][0], bl_[nt][1]);
            }
        }
        __syncthreads();
    }

#pragma unroll
    for (int mt = 0; mt < 4; mt++) {
#pragma unroll
        for (int half = 0; half < 2; half++) {
            const int gm = bm + wm + mt * 16 + G + half * 8;
            const int b_ = gm >> 11;
            const int s_ = gm & 2047;
#pragma unroll
            for (int nt = 0; nt < 4; nt++) {
                const int gn = bn + wn + nt * 8 + 2 * T;
                float2 bv = *(const float2*)&bias[gn];
                float vx = c[mt][nt][half * 2 + 0] + bv.x;
                float vy = c[mt][nt][half * 2 + 1] + bv.y;
                const int h = gn >> 6, d = gn & 63;
                if (mode == 0) {
                    float2 v; v.x = vx; v.y = vy;
                    *(float2*)((float*)C + (size_t)gm * DMODEL + gn) = v;
                } else if (mode == 1) {
                    __half2 v = __floats2half2_rn(vx * 0.125f, vy * 0.125f);
                    *(__half2*)((__half*)C + (((size_t)(b_ * NHEAD + h) * SEQ) + s_) * DK + d) = v;
                } else if (mode == 2) {
                    __half2 v = __floats2half2_rn(vx, vy);
                    *(__half2*)((__half*)C + (((size_t)(b_ * NHEAD + h) * SEQ) + s_) * DK + d) = v;
                } else {
                    __half* Cb = (__half*)C + ((size_t)(b_ * NHEAD + h) * DK + d) * SEQ + s_;
                    Cb[0]   = __float2half_rn(vx);
                    Cb[SEQ] = __float2half_rn(vy);
                }
            }
        }
    }
}

// ---------------- FP16 mma flash attention (ldmatrix, unchanged) ------------
#define AST2 72
#define A_PS 0
#define A_K0 (128 * AST2)
#define A_KB (64 * AST2)
#define A_V0 (A_K0 + 2 * A_KB)
#define A_VB (64 * AST2)
#define A_SMEM ((A_V0 + 2 * A_VB) * 2)   // 55296 B

__global__ void __launch_bounds__(256, 2) attn_mma(
    const __half* __restrict__ Qg, const __half* __restrict__ Kg,
    const __half* __restrict__ Vg, bf16* __restrict__ Ohi,
    bf16* __restrict__ Olo)
{
    extern __shared__ __half sh[];
    const uint32_t base = smem_u32(sh);
    __half* Ps = sh + A_PS;

    const int tid = threadIdx.x;
    const int w = tid >> 5;
    const int lane = tid & 31;
    const int G = lane >> 2;
    const int T = lane & 3;
    const int bh = blockIdx.y;
    const int q0 = blockIdx.x * 128;
    const int wrow = w * 16;

    const __half* Qb = Qg + ((size_t)bh * SEQ + q0) * DK;
    const __half* Kb = Kg + (size_t)bh * SEQ * DK;
    const __half* Vb = Vg + (size_t)bh * DK * SEQ;

    const int ld = tid >> 2;
    const int lh = (tid & 3) * 16;

    const int a_r = lane & 15;
    const int a_c = (lane & 16) ? 8 : 0;
    const int b_r = (lane & 7) + ((lane & 16) ? 8 : 0);
    const int b_c = (lane & 8) ? 8 : 0;
    const uint32_t pa0 = base + (uint32_t)((wrow + a_r) * AST2 + a_c) * 2;

    {
        const int qr = tid >> 1;
        const int qh = (tid & 1) * 32;
        const __half* qsrc = Qb + (size_t)qr * DK + qh;
        const uint32_t qdst = base + (uint32_t)(qr * AST2 + qh) * 2;
#pragma unroll
        for (int c = 0; c < 4; c++) CP_ASYNC16(qdst + c * 16, qsrc + c * 8);
    }
    {
        const __half* ks = Kb + (size_t)ld * DK + lh;
        const uint32_t kd = base + (uint32_t)(A_K0 + ld * AST2 + lh) * 2;
        const __half* vs = Vb + (size_t)ld * SEQ + lh;
        const uint32_t vd = base + (uint32_t)(A_V0 + ld * AST2 + lh) * 2;
        CP_ASYNC16(kd, ks); CP_ASYNC16(kd + 16, ks + 8);
        CP_ASYNC16(vd, vs); CP_ASYNC16(vd + 16, vs + 8);
    }
    CP_COMMIT();
    {
        const __half* ks = Kb + (size_t)(64 + ld) * DK + lh;
        const uint32_t kd = base + (uint32_t)(A_K0 + A_KB + ld * AST2 + lh) * 2;
        const __half* vs = Vb + (size_t)ld * SEQ + 64 + lh;
        const uint32_t vd = base + (uint32_t)(A_V0 + A_VB + ld * AST2 + lh) * 2;
        CP_ASYNC16(kd, ks); CP_ASYNC16(kd + 16, ks + 8);
        CP_ASYNC16(vd, vs); CP_ASYNC16(vd + 16, vs + 8);
    }
    CP_COMMIT();
    CP_WAIT(1);
    __syncthreads();

    uint32_t qa[4][4];
#pragma unroll
    for (int ki = 0; ki < 4; ki++)
        LDSM_X4(qa[ki][0], qa[ki][1], qa[ki][2], qa[ki][3],
                pa0 + (uint32_t)(ki * 16) * 2);

    float m_i[2] = {-1e30f, -1e30f};
    float l_i[2] = {0.0f, 0.0f};
    float acc[8][4];
#pragma unroll
    for (int dt = 0; dt < 8; dt++)
#pragma unroll
        for (int i = 0; i < 4; i++) acc[dt][i] = 0.0f;

    const int NKT = SEQ / 64;
    for (int it = 0; it < NKT; it++) {
        if (it) { CP_WAIT(1); __syncthreads(); }

        const uint32_t kbase = base + (uint32_t)(A_K0 + (it & 1) * A_KB) * 2
                             + (uint32_t)(b_r * AST2 + b_c) * 2;
        const uint32_t vbase = base + (uint32_t)(A_V0 + (it & 1) * A_VB) * 2
                             + (uint32_t)(b_r * AST2 + b_c) * 2;

        float s[8][4];
#pragma unroll
        for (int nt = 0; nt < 8; nt++)
#pragma unroll
            for (int i = 0; i < 4; i++) s[nt][i] = 0.0f;

#pragma unroll
        for (int ki = 0; ki < 4; ki++) {
            const int ko = ki * 16;
            uint32_t kb[8][2];
#pragma unroll
            for (int ntp = 0; ntp < 4; ntp++)
                LDSM_X4(kb[2 * ntp][0], kb[2 * ntp][1],
                        kb[2 * ntp + 1][0], kb[2 * ntp + 1][1],
                        kbase + (uint32_t)(ntp * 16 * AST2 + ko) * 2);
#pragma unroll
            for (int nt = 0; nt < 8; nt++)
                mma_f16(s[nt], qa[ki][0], qa[ki][1], qa[ki][2], qa[ki][3],
                        kb[nt][0], kb[nt][1]);
        }

        float fac[2];
#pragma unroll
        for (int r = 0; r < 2; r++) {
            float mx = -1e30f;
#pragma unroll
            for (int nt = 0; nt < 8; nt++)
                mx = fmaxf(mx, fmaxf(s[nt][2 * r], s[nt][2 * r + 1]));
            mx = fmaxf(mx, __shfl_xor_sync(0xffffffffu, mx, 1));
            mx = fmaxf(mx, __shfl_xor_sync(0xffffffffu, mx, 2));
            const float mn = fmaxf(m_i[r], mx);
            fac[r] = __expf(m_i[r] - mn);
            m_i[r] = mn;
            float ls = 0.0f;
#pragma unroll
            for (int nt = 0; nt < 8; nt++) {
                float p0 = __half2float(__float2half_rn(__expf(s[nt][2 * r + 0] - mn)));
                float p1 = __half2float(__float2half_rn(__expf(s[nt][2 * r + 1] - mn)));
                s[nt][2 * r + 0] = p0;
                s[nt][2 * r + 1] = p1;
                ls += p0 + p1;
            }
            ls += __shfl_xor_sync(0xffffffffu, ls, 1);
            ls += __shfl_xor_sync(0xffffffffu, ls, 2);
            l_i[r] = l_i[r] * fac[r] + ls;
        }

#pragma unroll
        for (int nt = 0; nt < 8; nt++) {
            *(__half2*)(Ps + (wrow + G) * AST2 + nt * 8 + 2 * T) =
                __floats2half2_rn(s[nt][0], s[nt][1]);
            *(__half2*)(Ps + (wrow + G + 8) * AST2 + nt * 8 + 2 * T) =
                __floats2half2_rn(s[nt][2], s[nt][3]);
        }
        __syncwarp();

#pragma unroll
        for (int dt = 0; dt < 8; dt++) {
            acc[dt][0] *= fac[0];
            acc[dt][1] *= fac[0];
            acc[dt][2] *= fac[1];
            acc[dt][3] *= fac[1];
        }

#pragma unroll
        for (int ki = 0; ki < 4; ki++) {
            const int ko = ki * 16;
            uint32_t a0, a1, a2, a3;
            LDSM_X4(a0, a1, a2, a3, pa0 + (uint32_t)ko * 2);
            uint32_t vb[8][2];
#pragma unroll
            for (int dtp = 0; dtp < 4; dtp++)
                LDSM_X4(vb[2 * dtp][0], vb[2 * dtp][1],
                        vb[2 * dtp + 1][0], vb[2 * dtp + 1][1],
                        vbase + (uint32_t)(dtp * 16 * AST2 + ko) * 2);
#pragma unroll
            for (int dt = 0; dt < 8; dt++)
                mma_f16(acc[dt], a0, a1, a2, a3, vb[dt][0], vb[dt][1]);
        }

        __syncthreads();
        if (it + 2 < NKT) {
            const int kt2 = (it + 2) * 64;
            const __half* ks = Kb + (size_t)(kt2 + ld) * DK + lh;
            const uint32_t kd = base + (uint32_t)(A_K0 + (it & 1) * A_KB + ld * AST2 + lh) * 2;
            const __half* vs = Vb + (size_t)ld * SEQ + kt2 + lh;
            const uint32_t vd = base + (uint32_t)(A_V0 + (it & 1) * A_VB + ld * AST2 + lh) * 2;
            CP_ASYNC16(kd, ks); CP_ASYNC16(kd + 16, ks + 8);
            CP_ASYNC16(vd, vs); CP_ASYNC16(vd + 16, vs + 8);
        }
        CP_COMMIT();
    }

    const int b = bh >> 4;
    const int h = bh & 15;
    const float inv0 = 1.0f / l_i[0];
    const float inv1 = 1.0f / l_i[1];
    const int r0 = q0 + wrow + G;
    const int r1 = r0 + 8;
    const size_t o0 = ((size_t)b * SEQ + r0) * DMODEL + h * DK;
    const size_t o1 = ((size_t)b * SEQ + r1) * DMODEL + h * DK;
#pragma unroll
    for (int dt = 0; dt < 8; dt++) {
        const int d = dt * 8 + 2 * T;
        float x0 = acc[dt][0] * inv0, y0 = acc[dt][1] * inv0;
        float x1 = acc[dt][2] * inv1, y1 = acc[dt][3] * inv1;
        __nv_bfloat162 h0, l0, h1, l1;
        bf16 hh, ll;
        bf16_split(x0, hh, ll); h0.x = hh; l0.x = ll;
        bf16_split(y0, hh, ll); h0.y = hh; l0.y = ll;
        bf16_split(x1, hh, ll); h1.x = hh; l1.x = ll;
        bf16_split(y1, hh, ll); h1.y = hh; l1.y = ll;
        *(__nv_bfloat162*)&Ohi[o0 + d] = h0;
        *(__nv_bfloat162*)&Olo[o0 + d] = l0;
        *(__nv_bfloat162*)&Ohi[o1 + d] = h1;
        *(__nv_bfloat162*)&Olo[o1 + d] = l1;
    }
}

// ---------------- launch ----------------
extern "C" void kernel_launch(void* const* d_in, const int* in_sizes, int n_in,
                              void* d_out, int out_size)
{
    const float* x  = (const float*)d_in[0];
    const float* Wq = (const float*)d_in[1];
    const float* bq = (const float*)d_in[2];
    const float* Wk = (const float*)d_in[3];
    const float* bk = (const float*)d_in[4];
    const float* Wv = (const float*)d_in[5];
    const float* bv = (const float*)d_in[6];
    const float* Wo = (const float*)d_in[7];
    const float* bo = (const float*)d_in[8];
    float* out = (float*)d_out;

    __half *gq, *gk, *gv;
    bf16 *gxh, *gxl, *gah, *gal;
    bf16 *wqh, *wql, *wkh, *wkl, *wvh, *wvl, *woh, *wol;
    cudaGetSymbolAddress((void**)&gq,  g_q);
    cudaGetSymbolAddress((void**)&gk,  g_k);
    cudaGetSymbolAddress((void**)&gv,  g_v);
    cudaGetSymbolAddress((void**)&gxh, g_xh);
    cudaGetSymbolAddress((void**)&gxl, g_xl);
    cudaGetSymbolAddress((void**)&gah, g_aoh);
    cudaGetSymbolAddress((void**)&gal, g_aol);
    cudaGetSymbolAddress((void**)&wqh, g_wqh);
    cudaGetSymbolAddress((void**)&wql, g_wql);
    cudaGetSymbolAddress((void**)&wkh, g_wkh);
    cudaGetSymbolAddress((void**)&wkl, g_wkl);
    cudaGetSymbolAddress((void**)&wvh, g_wvh);
    cudaGetSymbolAddress((void**)&wvl, g_wvl);
    cudaGetSymbolAddress((void**)&woh, g_woh);
    cudaGetSymbolAddress((void**)&wol, g_wol);

    cudaFuncSetAttribute(gemm3_bf16, cudaFuncAttributeMaxDynamicSharedMemorySize,
                         B_SMEM);
    cudaFuncSetAttribute(attn_mma, cudaFuncAttributeMaxDynamicSharedMemorySize,
                         A_SMEM);

    split_all_kernel<<<(NTASK + 255) / 256, 256>>>(
        x, Wq, Wk, Wv, Wo, gxh, gxl,
        wqh, wql, wkh, wkl, wvh, wvl, woh, wol);

    dim3 gqkv(DMODEL / 128, MROWS / 128, 3);
    gemm3_bf16<<<gqkv, 256, B_SMEM>>>(gxh, gxl,
                                      wqh, wql, bq, gq,
                                      wkh, wkl, bk, gk,
                                      wvh, wvl, bv, gv, 1, 2, 3);

    attn_mma<<<dim3(SEQ / 128, BATCH * NHEAD), 256, A_SMEM>>>(gq, gk, gv, gah, gal);

    dim3 go(DMODEL / 128, MROWS / 128, 1);
    gemm3_bf16<<<go, 256, B_SMEM>>>(gah, gal,
                                    woh, wol, bo, out,
                                    woh, wol, bo, out,
                                    woh, wol, bo, out, 0, 0, 0);
}

// round 13
// speedup vs baseline: 1.2279x; 1.2279x over previous
#include <cuda_runtime.h>
#include <cuda_bf16.h>
#include <cuda_fp16.h>
#include <cstdint>
#include <cstddef>

#define BATCH  2
#define SEQ    2048
#define DMODEL 1024
#define NHEAD  16
#define DK     64
#define MROWS  (BATCH * SEQ)
#define KDIM   1024

__device__ __half g_q[BATCH * NHEAD * SEQ * DK];
__device__ __half g_k[BATCH * NHEAD * SEQ * DK];
__device__ __half g_v[BATCH * NHEAD * DK * SEQ];
__device__ __half g_xh[MROWS * DMODEL];
__device__ __half g_xl[MROWS * DMODEL];
__device__ __half g_aoh[MROWS * DMODEL];
__device__ __half g_aol[MROWS * DMODEL];
__device__ __half g_wq[DMODEL * DMODEL];
__device__ __half g_wk[DMODEL * DMODEL];
__device__ __half g_wv[DMODEL * DMODEL];
__device__ __half g_wo[DMODEL * DMODEL];

__device__ __forceinline__ uint32_t smem_u32(const void* p) {
    uint32_t a;
    asm("{ .reg .u64 t; cvta.to.shared.u64 t, %1; cvt.u32.u64 %0, t; }"
        : "=r"(a) : "l"(p));
    return a;
}

#define CP_ASYNC16(dst_u32, src_ptr) \
    asm volatile("cp.async.cg.shared.global [%0], [%1], 16;" \
        :: "r"(dst_u32), "l"((const void*)(src_ptr)) : "memory")
#define CP_COMMIT() asm volatile("cp.async.commit_group;" ::: "memory")
#define CP_WAIT(n)  asm volatile("cp.async.wait_group %0;" :: "n"(n) : "memory")

#define LDSM_X4(r0, r1, r2, r3, addr) \
    asm volatile("ldmatrix.sync.aligned.m8n8.x4.shared.b16 {%0,%1,%2,%3}, [%4];" \
        : "=r"(r0), "=r"(r1), "=r"(r2), "=r"(r3) : "r"(addr))

__device__ __forceinline__ void mma_f16(float c[4], uint32_t a0, uint32_t a1,
                                        uint32_t a2, uint32_t a3,
                                        uint32_t b0, uint32_t b1) {
    asm volatile(
        "mma.sync.aligned.m16n8k16.row.col.f32.f16.f16.f32 "
        "{%0,%1,%2,%3}, {%4,%5,%6,%7}, {%8,%9}, {%0,%1,%2,%3};"
        : "+f"(c[0]), "+f"(c[1]), "+f"(c[2]), "+f"(c[3])
        : "r"(a0), "r"(a1), "r"(a2), "r"(a3), "r"(b0), "r"(b1));
}

__device__ __forceinline__ void f16_split(float v, __half& h, __half& l) {
    h = __float2half_rn(v);
    l = __float2half_rn(v - __half2float(h));
}

// ---------------- pre-pass: x -> fp16 hi/lo ; W -> fp16 ----------------
#define NX4 ((MROWS * DMODEL) / 4)
#define NW4 ((DMODEL * DMODEL) / 4)
#define NTASK (NX4 + 4 * NW4)

__global__ void split_all_kernel(
    const float* __restrict__ x,
    const float* __restrict__ Wq, const float* __restrict__ Wk,
    const float* __restrict__ Wv, const float* __restrict__ Wo,
    __half* __restrict__ xh, __half* __restrict__ xl,
    __half* __restrict__ wq, __half* __restrict__ wk,
    __half* __restrict__ wv, __half* __restrict__ wo)
{
    int i = blockIdx.x * blockDim.x + threadIdx.x;
    if (i >= NTASK) return;
    if (i < NX4) {
        float4 v = ((const float4*)x)[i];
        __half2 h0, h1, l0, l1;
        __half h, l;
        f16_split(v.x, h, l); h0.x = h; l0.x = l;
        f16_split(v.y, h, l); h0.y = h; l0.y = l;
        f16_split(v.z, h, l); h1.x = h; l1.x = l;
        f16_split(v.w, h, l); h1.y = h; l1.y = l;
        ((__half2*)xh)[2 * i + 0] = h0;
        ((__half2*)xh)[2 * i + 1] = h1;
        ((__half2*)xl)[2 * i + 0] = l0;
        ((__half2*)xl)[2 * i + 1] = l1;
    } else {
        int j = i - NX4;
        int t = j / NW4;
        int o = j - t * NW4;
        const float* in = (t == 0) ? Wq : (t == 1) ? Wk : (t == 2) ? Wv : Wo;
        __half* oh = (t == 0) ? wq : (t == 1) ? wk : (t == 2) ? wv : wo;
        float4 v = ((const float4*)in)[o];
        ((__half2*)oh)[2 * o + 0] = __floats2half2_rn(v.x, v.y);
        ((__half2*)oh)[2 * o + 1] = __floats2half2_rn(v.z, v.w);
    }
}

// ---------------- 2-term FP16 GEMM: C = (Ah+Al)*W^T + bias ----------------
// modes: 0 fp32 row-major+bias; 1 Q fp16 [B,H,s,d]*0.125; 2 K fp16 [B,H,s,d];
//        3 V fp16 [B,H,d,s]
#define BBK 32
#define BRS 40
#define B_TILE (128 * BRS)
#define B_STAGE (3 * B_TILE)          // Ah, Al, W
#define B_SMEM (2 * B_STAGE * 2)      // 61440 B

__device__ __forceinline__ void gemmb_load(
    const __half* __restrict__ Ah, const __half* __restrict__ Al,
    const __half* __restrict__ Wm,
    int bm, int bn, uint32_t base, int tid, int k0, int s)
{
    const __half* bases[3] = {
        Ah + (size_t)bm * KDIM, Al + (size_t)bm * KDIM,
        Wm + (size_t)bn * KDIM };
    const uint32_t st = base + (uint32_t)(s * B_STAGE) * 2;
#pragma unroll
    for (int i = 0; i < 6; i++) {
        const int task = tid + 256 * i;     // 0..1535
        const int t = task >> 9;
        const int rem = task & 511;
        const int r = rem >> 2;
        const int seg = rem & 3;
        const __half* src = bases[t] + (size_t)r * KDIM + k0 + seg * 8;
        const uint32_t dst = st + (uint32_t)(t * B_TILE + r * BRS + seg * 8) * 2;
        CP_ASYNC16(dst, src);
    }
}

__global__ void __launch_bounds__(256, 2) gemm2_f16(
    const __half* __restrict__ Ah, const __half* __restrict__ Al,
    const __half* __restrict__ W0, const float* __restrict__ b0v,
    void* __restrict__ C0,
    const __half* __restrict__ W1, const float* __restrict__ b1v,
    void* __restrict__ C1,
    const __half* __restrict__ W2, const float* __restrict__ b2v,
    void* __restrict__ C2,
    int m0, int m1, int m2)
{
    extern __shared__ char smem_raw[];
    const uint32_t base = smem_u32(smem_raw);
    const int tid = threadIdx.x;
    const int wid = tid >> 5;
    const int lane = tid & 31;
    const int G = lane >> 2;
    const int T = lane & 3;
    const int wm = (wid >> 2) * 64;
    const int wn = (wid & 3) * 32;
    const int bm = blockIdx.y * 128;
    const int bn = blockIdx.x * 128;
    const int z = blockIdx.z;

    const __half* Wm = (z == 0) ? W0 : (z == 1) ? W1 : W2;
    const float* bias = (z == 0) ? b0v : (z == 1) ? b1v : b2v;
    void* C = (z == 0) ? C0 : (z == 1) ? C1 : C2;
    const int mode = (z == 0) ? m0 : (z == 1) ? m1 : m2;

    const int a_r = lane & 15;
    const int a_c = (lane & 16) ? 8 : 0;
    const int b_r = (lane & 7) + ((lane & 16) ? 8 : 0);
    const int b_c = (lane & 8) ? 8 : 0;
    const uint32_t a_addr0 = base + (uint32_t)((wm + a_r) * BRS + a_c) * 2;
    const uint32_t b_addr0 = base + (uint32_t)((wn + b_r) * BRS + b_c) * 2
                           + (uint32_t)(2 * B_TILE) * 2;

    float c[4][4][4];
#pragma unroll
    for (int mt = 0; mt < 4; mt++)
#pragma unroll
        for (int nt = 0; nt < 4; nt++)
#pragma unroll
            for (int i = 0; i < 4; i++) c[mt][nt][i] = 0.0f;

    gemmb_load(Ah, Al, Wm, bm, bn, base, tid, 0, 0);
    CP_COMMIT();

    const int NIT = KDIM / BBK;   // 32
    for (int k = 0; k < NIT; k++) {
        if (k + 1 < NIT) {
            gemmb_load(Ah, Al, Wm, bm, bn, base, tid, (k + 1) * BBK, (k + 1) & 1);
            CP_COMMIT();
            CP_WAIT(1);
        } else {
            CP_WAIT(0);
        }
        __syncthreads();

        const uint32_t sb = (uint32_t)((k & 1) * B_STAGE) * 2;
        const uint32_t tile2 = (uint32_t)B_TILE * 2;

#pragma unroll
        for (int ko = 0; ko < BBK; ko += 16) {
            uint32_t bw[4][2];
#pragma unroll
            for (int ntp = 0; ntp < 2; ntp++) {
                const uint32_t ba = b_addr0 + sb + (uint32_t)(ntp * 16 * BRS + ko) * 2;
                LDSM_X4(bw[2 * ntp][0], bw[2 * ntp][1],
                        bw[2 * ntp + 1][0], bw[2 * ntp + 1][1], ba);
            }
#pragma unroll
            for (int mt = 0; mt < 4; mt++) {
                const uint32_t aa = a_addr0 + sb + (uint32_t)(mt * 16 * BRS + ko) * 2;
                uint32_t ah0, ah1, ah2, ah3, al0, al1, al2, al3;
                LDSM_X4(ah0, ah1, ah2, ah3, aa);
                LDSM_X4(al0, al1, al2, al3, aa + tile2);
#pragma unroll
                for (int nt = 0; nt < 4; nt++)
                    mma_f16(c[mt][nt], ah0, ah1, ah2, ah3, bw[nt][0], bw[nt][1]);
#pragma unroll
                for (int nt = 0; nt < 4; nt++)
                    mma_f16(c[mt][nt], al0, al1, al2, al3, bw[nt][0], bw[nt][1]);
            }
        }
        __syncthreads();
    }

#pragma unroll
    for (int mt = 0; mt < 4; mt++) {
#pragma unroll
        for (int half = 0; half < 2; half++) {
            const int gm = bm + wm + mt * 16 + G + half * 8;
            const int b_ = gm >> 11;
            const int s_ = gm & 2047;
#pragma unroll
            for (int nt = 0; nt < 4; nt++) {
                const int gn = bn + wn + nt * 8 + 2 * T;
                float2 bv = *(const float2*)&bias[gn];
                float vx = c[mt][nt][half * 2 + 0] + bv.x;
                float vy = c[mt][nt][half * 2 + 1] + bv.y;
                const int h = gn >> 6, d = gn & 63;
                if (mode == 0) {
                    float2 v; v.x = vx; v.y = vy;
                    *(float2*)((float*)C + (size_t)gm * DMODEL + gn) = v;
                } else if (mode == 1) {
                    __half2 v = __floats2half2_rn(vx * 0.125f, vy * 0.125f);
                    *(__half2*)((__half*)C + (((size_t)(b_ * NHEAD + h) * SEQ) + s_) * DK + d) = v;
                } else if (mode == 2) {
                    __half2 v = __floats2half2_rn(vx, vy);
                    *(__half2*)((__half*)C + (((size_t)(b_ * NHEAD + h) * SEQ) + s_) * DK + d) = v;
                } else {
                    __half* Cb = (__half*)C + ((size_t)(b_ * NHEAD + h) * DK + d) * SEQ + s_;
                    Cb[0]   = __float2half_rn(vx);
                    Cb[SEQ] = __float2half_rn(vy);
                }
            }
        }
    }
}

// ---------------- FP16 mma flash attention (unchanged math) ----------------
#define AST2 72
#define A_PS 0
#define A_K0 (128 * AST2)
#define A_KB (64 * AST2)
#define A_V0 (A_K0 + 2 * A_KB)
#define A_VB (64 * AST2)
#define A_SMEM ((A_V0 + 2 * A_VB) * 2)   // 55296 B

__global__ void __launch_bounds__(256, 2) attn_mma(
    const __half* __restrict__ Qg, const __half* __restrict__ Kg,
    const __half* __restrict__ Vg, __half* __restrict__ Ohi,
    __half* __restrict__ Olo)
{
    extern __shared__ __half sh[];
    const uint32_t base = smem_u32(sh);
    __half* Ps = sh + A_PS;

    const int tid = threadIdx.x;
    const int w = tid >> 5;
    const int lane = tid & 31;
    const int G = lane >> 2;
    const int T = lane & 3;
    const int bh = blockIdx.y;
    const int q0 = blockIdx.x * 128;
    const int wrow = w * 16;

    const __half* Qb = Qg + ((size_t)bh * SEQ + q0) * DK;
    const __half* Kb = Kg + (size_t)bh * SEQ * DK;
    const __half* Vb = Vg + (size_t)bh * DK * SEQ;

    const int ld = tid >> 2;
    const int lh = (tid & 3) * 16;

    const int a_r = lane & 15;
    const int a_c = (lane & 16) ? 8 : 0;
    const int b_r = (lane & 7) + ((lane & 16) ? 8 : 0);
    const int b_c = (lane & 8) ? 8 : 0;
    const uint32_t pa0 = base + (uint32_t)((wrow + a_r) * AST2 + a_c) * 2;

    {
        const int qr = tid >> 1;
        const int qh = (tid & 1) * 32;
        const __half* qsrc = Qb + (size_t)qr * DK + qh;
        const uint32_t qdst = base + (uint32_t)(qr * AST2 + qh) * 2;
#pragma unroll
        for (int c = 0; c < 4; c++) CP_ASYNC16(qdst + c * 16, qsrc + c * 8);
    }
    {
        const __half* ks = Kb + (size_t)ld * DK + lh;
        const uint32_t kd = base + (uint32_t)(A_K0 + ld * AST2 + lh) * 2;
        const __half* vs = Vb + (size_t)ld * SEQ + lh;
        const uint32_t vd = base + (uint32_t)(A_V0 + ld * AST2 + lh) * 2;
        CP_ASYNC16(kd, ks); CP_ASYNC16(kd + 16, ks + 8);
        CP_ASYNC16(vd, vs); CP_ASYNC16(vd + 16, vs + 8);
    }
    CP_COMMIT();
    {
        const __half* ks = Kb + (size_t)(64 + ld) * DK + lh;
        const uint32_t kd = base + (uint32_t)(A_K0 + A_KB + ld * AST2 + lh) * 2;
        const __half* vs = Vb + (size_t)ld * SEQ + 64 + lh;
        const uint32_t vd = base + (uint32_t)(A_V0 + A_VB + ld * AST2 + lh) * 2;
        CP_ASYNC16(kd, ks); CP_ASYNC16(kd + 16, ks + 8);
        CP_ASYNC16(vd, vs); CP_ASYNC16(vd + 16, vs + 8);
    }
    CP_COMMIT();
    CP_WAIT(1);
    __syncthreads();

    uint32_t qa[4][4];
#pragma unroll
    for (int ki = 0; ki < 4; ki++)
        LDSM_X4(qa[ki][0], qa[ki][1], qa[ki][2], qa[ki][3],
                pa0 + (uint32_t)(ki * 16) * 2);

    float m_i[2] = {-1e30f, -1e30f};
    float l_i[2] = {0.0f, 0.0f};
    float acc[8][4];
#pragma unroll
    for (int dt = 0; dt < 8; dt++)
#pragma unroll
        for (int i = 0; i < 4; i++) acc[dt][i] = 0.0f;

    const int NKT = SEQ / 64;
    for (int it = 0; it < NKT; it++) {
        if (it) { CP_WAIT(1); __syncthreads(); }

        const uint32_t kbase = base + (uint32_t)(A_K0 + (it & 1) * A_KB) * 2
                             + (uint32_t)(b_r * AST2 + b_c) * 2;
        const uint32_t vbase = base + (uint32_t)(A_V0 + (it & 1) * A_VB) * 2
                             + (uint32_t)(b_r * AST2 + b_c) * 2;

        float s[8][4];
#pragma unroll
        for (int nt = 0; nt < 8; nt++)
#pragma unroll
            for (int i = 0; i < 4; i++) s[nt][i] = 0.0f;

#pragma unroll
        for (int ki = 0; ki < 4; ki++) {
            const int ko = ki * 16;
            uint32_t kb[8][2];
#pragma unroll
            for (int ntp = 0; ntp < 4; ntp++)
                LDSM_X4(kb[2 * ntp][0], kb[2 * ntp][1],
                        kb[2 * ntp + 1][0], kb[2 * ntp + 1][1],
                        kbase + (uint32_t)(ntp * 16 * AST2 + ko) * 2);
#pragma unroll
            for (int nt = 0; nt < 8; nt++)
                mma_f16(s[nt], qa[ki][0], qa[ki][1], qa[ki][2], qa[ki][3],
                        kb[nt][0], kb[nt][1]);
        }

        float fac[2];
#pragma unroll
        for (int r = 0; r < 2; r++) {
            float mx = -1e30f;
#pragma unroll
            for (int nt = 0; nt < 8; nt++)
                mx = fmaxf(mx, fmaxf(s[nt][2 * r], s[nt][2 * r + 1]));
            mx = fmaxf(mx, __shfl_xor_sync(0xffffffffu, mx, 1));
            mx = fmaxf(mx, __shfl_xor_sync(0xffffffffu, mx, 2));
            const float mn = fmaxf(m_i[r], mx);
            fac[r] = __expf(m_i[r] - mn);
            m_i[r] = mn;
            float ls = 0.0f;
#pragma unroll
            for (int nt = 0; nt < 8; nt++) {
                float p0 = __half2float(__float2half_rn(__expf(s[nt][2 * r + 0] - mn)));
                float p1 = __half2float(__float2half_rn(__expf(s[nt][2 * r + 1] - mn)));
                s[nt][2 * r + 0] = p0;
                s[nt][2 * r + 1] = p1;
                ls += p0 + p1;
            }
            ls += __shfl_xor_sync(0xffffffffu, ls, 1);
            ls += __shfl_xor_sync(0xffffffffu, ls, 2);
            l_i[r] = l_i[r] * fac[r] + ls;
        }

#pragma unroll
        for (int nt = 0; nt < 8; nt++) {
            *(__half2*)(Ps + (wrow + G) * AST2 + nt * 8 + 2 * T) =
                __floats2half2_rn(s[nt][0], s[nt][1]);
            *(__half2*)(Ps + (wrow + G + 8) * AST2 + nt * 8 + 2 * T) =
                __floats2half2_rn(s[nt][2], s[nt][3]);
        }
        __syncwarp();

#pragma unroll
        for (int dt = 0; dt < 8; dt++) {
            acc[dt][0] *= fac[0];
            acc[dt][1] *= fac[0];
            acc[dt][2] *= fac[1];
            acc[dt][3] *= fac[1];
        }

#pragma unroll
        for (int ki = 0; ki < 4; ki++) {
            const int ko = ki * 16;
            uint32_t a0, a1, a2, a3;
            LDSM_X4(a0, a1, a2, a3, pa0 + (uint32_t)ko * 2);
            uint32_t vb[8][2];
#pragma unroll
            for (int dtp = 0; dtp < 4; dtp++)
                LDSM_X4(vb[2 * dtp][0], vb[2 * dtp][1],
                        vb[2 * dtp + 1][0], vb[2 * dtp + 1][1],
                        vbase + (uint32_t)(dtp * 16 * AST2 + ko) * 2);
#pragma unroll
            for (int dt = 0; dt < 8; dt++)
                mma_f16(acc[dt], a0, a1, a2, a3, vb[dt][0], vb[dt][1]);
        }

        __syncthreads();
        if (it + 2 < NKT) {
            const int kt2 = (it + 2) * 64;
            const __half* ks = Kb + (size_t)(kt2 + ld) * DK + lh;
            const uint32_t kd = base + (uint32_t)(A_K0 + (it & 1) * A_KB + ld * AST2 + lh) * 2;
            const __half* vs = Vb + (size_t)ld * SEQ + kt2 + lh;
            const uint32_t vd = base + (uint32_t)(A_V0 + (it & 1) * A_VB + ld * AST2 + lh) * 2;
            CP_ASYNC16(kd, ks); CP_ASYNC16(kd + 16, ks + 8);
            CP_ASYNC16(vd, vs); CP_ASYNC16(vd + 16, vs + 8);
        }
        CP_COMMIT();
    }

    // epilogue: normalize, fp16 hi/lo split (feeds 2-term fp16 out-proj)
    const int b = bh >> 4;
    const int h = bh & 15;
    const float inv0 = 1.0f / l_i[0];
    const float inv1 = 1.0f / l_i[1];
    const int r0 = q0 + wrow + G;
    const int r1 = r0 + 8;
    const size_t o0 = ((size_t)b * SEQ + r0) * DMODEL + h * DK;
    const size_t o1 = ((size_t)b * SEQ + r1) * DMODEL + h * DK;
#pragma unroll
    for (int dt = 0; dt < 8; dt++) {
        const int d = dt * 8 + 2 * T;
        float x0 = acc[dt][0] * inv0, y0 = acc[dt][1] * inv0;
        float x1 = acc[dt][2] * inv1, y1 = acc[dt][3] * inv1;
        __half2 h0, l0, h1, l1;
        __half hh, ll;
        f16_split(x0, hh, ll); h0.x = hh; l0.x = ll;
        f16_split(y0, hh, ll); h0.y = hh; l0.y = ll;
        f16_split(x1, hh, ll); h1.x = hh; l1.x = ll;
        f16_split(y1, hh, ll); h1.y = hh; l1.y = ll;
        *(__half2*)&Ohi[o0 + d] = h0;
        *(__half2*)&Olo[o0 + d] = l0;
        *(__half2*)&Ohi[o1 + d] = h1;
        *(__half2*)&Olo[o1 + d] = l1;
    }
}

// ---------------- launch ----------------
extern "C" void kernel_launch(void* const* d_in, const int* in_sizes, int n_in,
                              void* d_out, int out_size)
{
    const float* x  = (const float*)d_in[0];
    const float* Wq = (const float*)d_in[1];
    const float* bq = (const float*)d_in[2];
    const float* Wk = (const float*)d_in[3];
    const float* bk = (const float*)d_in[4];
    const float* Wv = (const float*)d_in[5];
    const float* bv = (const float*)d_in[6];
    const float* Wo = (const float*)d_in[7];
    const float* bo = (const float*)d_in[8];
    float* out = (float*)d_out;

    __half *gq, *gk, *gv, *gxh, *gxl, *gah, *gal, *wq, *wk, *wv, *wo;
    cudaGetSymbolAddress((void**)&gq,  g_q);
    cudaGetSymbolAddress((void**)&gk,  g_k);
    cudaGetSymbolAddress((void**)&gv,  g_v);
    cudaGetSymbolAddress((void**)&gxh, g_xh);
    cudaGetSymbolAddress((void**)&gxl, g_xl);
    cudaGetSymbolAddress((void**)&gah, g_aoh);
    cudaGetSymbolAddress((void**)&gal, g_aol);
    cudaGetSymbolAddress((void**)&wq,  g_wq);
    cudaGetSymbolAddress((void**)&wk,  g_wk);
    cudaGetSymbolAddress((void**)&wv,  g_wv);
    cudaGetSymbolAddress((void**)&wo,  g_wo);

    cudaFuncSetAttribute(gemm2_f16, cudaFuncAttributeMaxDynamicSharedMemorySize,
                         B_SMEM);
    cudaFuncSetAttribute(attn_mma, cudaFuncAttributeMaxDynamicSharedMemorySize,
                         A_SMEM);

    split_all_kernel<<<(NTASK + 255) / 256, 256>>>(
        x, Wq, Wk, Wv, Wo, gxh, gxl, wq, wk, wv, wo);

    dim3 gqkv(DMODEL / 128, MROWS / 128, 3);
    gemm2_f16<<<gqkv, 256, B_SMEM>>>(gxh, gxl,
                                     wq, bq, gq,
                                     wk, bk, gk,
                                     wv, bv, gv, 1, 2, 3);

    attn_mma<<<dim3(SEQ / 128, BATCH * NHEAD), 256, A_SMEM>>>(gq, gk, gv, gah, gal);

    dim3 go(DMODEL / 128, MROWS / 128, 1);
    gemm2_f16<<<go, 256, B_SMEM>>>(gah, gal,
                                   wo, bo, out,
                                   wo, bo, out,
                                   wo, bo, out, 0, 0, 0);
}

// round 14
// speedup vs baseline: 1.3122x; 1.0687x over previous
#include <cuda_runtime.h>
#include <cuda_fp16.h>
#include <cstdint>
#include <cstddef>

#define BATCH  2
#define SEQ    2048
#define DMODEL 1024
#define NHEAD  16
#define DK     64
#define MROWS  (BATCH * SEQ)
#define KDIM   1024

__device__ __half g_q[BATCH * NHEAD * SEQ * DK];
__device__ __half g_k[BATCH * NHEAD * SEQ * DK];
__device__ __half g_v[BATCH * NHEAD * DK * SEQ];
__device__ __half g_xh[MROWS * DMODEL];
__device__ __half g_xl[MROWS * DMODEL];
__device__ __half g_aoh[MROWS * DMODEL];
__device__ __half g_aol[MROWS * DMODEL];
__device__ __half g_wq[DMODEL * DMODEL];
__device__ __half g_wk[DMODEL * DMODEL];
__device__ __half g_wv[DMODEL * DMODEL];
__device__ __half g_wo[DMODEL * DMODEL];

__device__ __forceinline__ uint32_t smem_u32(const void* p) {
    uint32_t a;
    asm("{ .reg .u64 t; cvta.to.shared.u64 t, %1; cvt.u32.u64 %0, t; }"
        : "=r"(a) : "l"(p));
    return a;
}

#define CP_ASYNC16(dst_u32, src_ptr) \
    asm volatile("cp.async.cg.shared.global [%0], [%1], 16;" \
        :: "r"(dst_u32), "l"((const void*)(src_ptr)) : "memory")
#define CP_COMMIT() asm volatile("cp.async.commit_group;" ::: "memory")
#define CP_WAIT(n)  asm volatile("cp.async.wait_group %0;" :: "n"(n) : "memory")

#define LDSM_X4(r0, r1, r2, r3, addr) \
    asm volatile("ldmatrix.sync.aligned.m8n8.x4.shared.b16 {%0,%1,%2,%3}, [%4];" \
        : "=r"(r0), "=r"(r1), "=r"(r2), "=r"(r3) : "r"(addr))

__device__ __forceinline__ void mma_f16(float c[4], uint32_t a0, uint32_t a1,
                                        uint32_t a2, uint32_t a3,
                                        uint32_t b0, uint32_t b1) {
    asm volatile(
        "mma.sync.aligned.m16n8k16.row.col.f32.f16.f16.f32 "
        "{%0,%1,%2,%3}, {%4,%5,%6,%7}, {%8,%9}, {%0,%1,%2,%3};"
        : "+f"(c[0]), "+f"(c[1]), "+f"(c[2]), "+f"(c[3])
        : "r"(a0), "r"(a1), "r"(a2), "r"(a3), "r"(b0), "r"(b1));
}

__device__ __forceinline__ void f16_split(float v, __half& h, __half& l) {
    h = __float2half_rn(v);
    l = __float2half_rn(v - __half2float(h));
}

// ---------------- pre-pass: x -> fp16 hi/lo ; W -> fp16 ----------------
#define NX4 ((MROWS * DMODEL) / 4)
#define NW4 ((DMODEL * DMODEL) / 4)
#define NTASK (NX4 + 4 * NW4)

__global__ void split_all_kernel(
    const float* __restrict__ x,
    const float* __restrict__ Wq, const float* __restrict__ Wk,
    const float* __restrict__ Wv, const float* __restrict__ Wo,
    __half* __restrict__ xh, __half* __restrict__ xl,
    __half* __restrict__ wq, __half* __restrict__ wk,
    __half* __restrict__ wv, __half* __restrict__ wo)
{
    int i = blockIdx.x * blockDim.x + threadIdx.x;
    if (i >= NTASK) return;
    if (i < NX4) {
        float4 v = ((const float4*)x)[i];
        __half2 h0, h1, l0, l1;
        __half h, l;
        f16_split(v.x, h, l); h0.x = h; l0.x = l;
        f16_split(v.y, h, l); h0.y = h; l0.y = l;
        f16_split(v.z, h, l); h1.x = h; l1.x = l;
        f16_split(v.w, h, l); h1.y = h; l1.y = l;
        ((__half2*)xh)[2 * i + 0] = h0;
        ((__half2*)xh)[2 * i + 1] = h1;
        ((__half2*)xl)[2 * i + 0] = l0;
        ((__half2*)xl)[2 * i + 1] = l1;
    } else {
        int j = i - NX4;
        int t = j / NW4;
        int o = j - t * NW4;
        const float* in = (t == 0) ? Wq : (t == 1) ? Wk : (t == 2) ? Wv : Wo;
        __half* oh = (t == 0) ? wq : (t == 1) ? wk : (t == 2) ? wv : wo;
        float4 v = ((const float4*)in)[o];
        ((__half2*)oh)[2 * o + 0] = __floats2half2_rn(v.x, v.y);
        ((__half2*)oh)[2 * o + 1] = __floats2half2_rn(v.z, v.w);
    }
}

// ---------------- 2-term FP16 GEMM, BBK=64: C = (Ah+Al)*W^T + bias ----------
// modes: 0 fp32 row-major+bias; 1 Q fp16 [B,H,s,d]*0.125; 2 K fp16 [B,H,s,d];
//        3 V fp16 [B,H,d,s]
#define BBK 64
#define BRS 72
#define B_TILE (128 * BRS)            // 9216 fp16
#define B_STAGE (3 * B_TILE)          // Ah, Al, W
#define B_SMEM (2 * B_STAGE * 2)      // 110592 B

__device__ __forceinline__ void gemmb_load(
    const __half* __restrict__ Ah, const __half* __restrict__ Al,
    const __half* __restrict__ Wm,
    int bm, int bn, uint32_t base, int tid, int k0, int s)
{
    const __half* bases[3] = {
        Ah + (size_t)bm * KDIM, Al + (size_t)bm * KDIM,
        Wm + (size_t)bn * KDIM };
    const uint32_t st = base + (uint32_t)(s * B_STAGE) * 2;
#pragma unroll
    for (int i = 0; i < 12; i++) {
        const int task = tid + 256 * i;     // 0..3071
        const int t = task >> 10;
        const int rem = task & 1023;
        const int r = rem >> 3;             // 0..127
        const int seg = rem & 7;            // 0..7 (8 fp16 each)
        const __half* src = bases[t] + (size_t)r * KDIM + k0 + seg * 8;
        const uint32_t dst = st + (uint32_t)(t * B_TILE + r * BRS + seg * 8) * 2;
        CP_ASYNC16(dst, src);
    }
}

__global__ void __launch_bounds__(256, 2) gemm2_f16(
    const __half* __restrict__ Ah, const __half* __restrict__ Al,
    const __half* __restrict__ W0, const float* __restrict__ b0v,
    void* __restrict__ C0,
    const __half* __restrict__ W1, const float* __restrict__ b1v,
    void* __restrict__ C1,
    const __half* __restrict__ W2, const float* __restrict__ b2v,
    void* __restrict__ C2,
    int m0, int m1, int m2)
{
    extern __shared__ char smem_raw[];
    const uint32_t base = smem_u32(smem_raw);
    const int tid = threadIdx.x;
    const int wid = tid >> 5;
    const int lane = tid & 31;
    const int G = lane >> 2;
    const int T = lane & 3;
    const int wm = (wid >> 2) * 64;
    const int wn = (wid & 3) * 32;
    const int bm = blockIdx.y * 128;
    const int bn = blockIdx.x * 128;
    const int z = blockIdx.z;

    const __half* Wm = (z == 0) ? W0 : (z == 1) ? W1 : W2;
    const float* bias = (z == 0) ? b0v : (z == 1) ? b1v : b2v;
    void* C = (z == 0) ? C0 : (z == 1) ? C1 : C2;
    const int mode = (z == 0) ? m0 : (z == 1) ? m1 : m2;

    const int a_r = lane & 15;
    const int a_c = (lane & 16) ? 8 : 0;
    const int b_r = (lane & 7) + ((lane & 16) ? 8 : 0);
    const int b_c = (lane & 8) ? 8 : 0;
    const uint32_t a_addr0 = base + (uint32_t)((wm + a_r) * BRS + a_c) * 2;
    const uint32_t b_addr0 = base + (uint32_t)((wn + b_r) * BRS + b_c) * 2
                           + (uint32_t)(2 * B_TILE) * 2;

    float c[4][4][4];
#pragma unroll
    for (int mt = 0; mt < 4; mt++)
#pragma unroll
        for (int nt = 0; nt < 4; nt++)
#pragma unroll
            for (int i = 0; i < 4; i++) c[mt][nt][i] = 0.0f;

    gemmb_load(Ah, Al, Wm, bm, bn, base, tid, 0, 0);
    CP_COMMIT();

    const int NIT = KDIM / BBK;   // 16
    for (int k = 0; k < NIT; k++) {
        if (k + 1 < NIT) {
            gemmb_load(Ah, Al, Wm, bm, bn, base, tid, (k + 1) * BBK, (k + 1) & 1);
            CP_COMMIT();
            CP_WAIT(1);
        } else {
            CP_WAIT(0);
        }
        __syncthreads();

        const uint32_t sb = (uint32_t)((k & 1) * B_STAGE) * 2;
        const uint32_t tile2 = (uint32_t)B_TILE * 2;

#pragma unroll
        for (int ko = 0; ko < BBK; ko += 16) {
            uint32_t bw[4][2];
#pragma unroll
            for (int ntp = 0; ntp < 2; ntp++) {
                const uint32_t ba = b_addr0 + sb + (uint32_t)(ntp * 16 * BRS + ko) * 2;
                LDSM_X4(bw[2 * ntp][0], bw[2 * ntp][1],
                        bw[2 * ntp + 1][0], bw[2 * ntp + 1][1], ba);
            }
#pragma unroll
            for (int mt = 0; mt < 4; mt++) {
                const uint32_t aa = a_addr0 + sb + (uint32_t)(mt * 16 * BRS + ko) * 2;
                uint32_t ah0, ah1, ah2, ah3, al0, al1, al2, al3;
                LDSM_X4(ah0, ah1, ah2, ah3, aa);
                LDSM_X4(al0, al1, al2, al3, aa + tile2);
#pragma unroll
                for (int nt = 0; nt < 4; nt++)
                    mma_f16(c[mt][nt], ah0, ah1, ah2, ah3, bw[nt][0], bw[nt][1]);
#pragma unroll
                for (int nt = 0; nt < 4; nt++)
                    mma_f16(c[mt][nt], al0, al1, al2, al3, bw[nt][0], bw[nt][1]);
            }
        }
        __syncthreads();
    }

#pragma unroll
    for (int mt = 0; mt < 4; mt++) {
#pragma unroll
        for (int half = 0; half < 2; half++) {
            const int gm = bm + wm + mt * 16 + G + half * 8;
            const int b_ = gm >> 11;
            const int s_ = gm & 2047;
#pragma unroll
            for (int nt = 0; nt < 4; nt++) {
                const int gn = bn + wn + nt * 8 + 2 * T;
                float2 bv = *(const float2*)&bias[gn];
                float vx = c[mt][nt][half * 2 + 0] + bv.x;
                float vy = c[mt][nt][half * 2 + 1] + bv.y;
                const int h = gn >> 6, d = gn & 63;
                if (mode == 0) {
                    float2 v; v.x = vx; v.y = vy;
                    *(float2*)((float*)C + (size_t)gm * DMODEL + gn) = v;
                } else if (mode == 1) {
                    __half2 v = __floats2half2_rn(vx * 0.125f, vy * 0.125f);
                    *(__half2*)((__half*)C + (((size_t)(b_ * NHEAD + h) * SEQ) + s_) * DK + d) = v;
                } else if (mode == 2) {
                    __half2 v = __floats2half2_rn(vx, vy);
                    *(__half2*)((__half*)C + (((size_t)(b_ * NHEAD + h) * SEQ) + s_) * DK + d) = v;
                } else {
                    __half* Cb = (__half*)C + ((size_t)(b_ * NHEAD + h) * DK + d) * SEQ + s_;
                    Cb[0]   = __float2half_rn(vx);
                    Cb[SEQ] = __float2half_rn(vy);
                }
            }
        }
    }
}

// ---------------- FP16 mma flash attention (unchanged) ----------------
#define AST2 72
#define A_PS 0
#define A_K0 (128 * AST2)
#define A_KB (64 * AST2)
#define A_V0 (A_K0 + 2 * A_KB)
#define A_VB (64 * AST2)
#define A_SMEM ((A_V0 + 2 * A_VB) * 2)   // 55296 B

__global__ void __launch_bounds__(256, 2) attn_mma(
    const __half* __restrict__ Qg, const __half* __restrict__ Kg,
    const __half* __restrict__ Vg, __half* __restrict__ Ohi,
    __half* __restrict__ Olo)
{
    extern __shared__ __half sh[];
    const uint32_t base = smem_u32(sh);
    __half* Ps = sh + A_PS;

    const int tid = threadIdx.x;
    const int w = tid >> 5;
    const int lane = tid & 31;
    const int G = lane >> 2;
    const int T = lane & 3;
    const int bh = blockIdx.y;
    const int q0 = blockIdx.x * 128;
    const int wrow = w * 16;

    const __half* Qb = Qg + ((size_t)bh * SEQ + q0) * DK;
    const __half* Kb = Kg + (size_t)bh * SEQ * DK;
    const __half* Vb = Vg + (size_t)bh * DK * SEQ;

    const int ld = tid >> 2;
    const int lh = (tid & 3) * 16;

    const int a_r = lane & 15;
    const int a_c = (lane & 16) ? 8 : 0;
    const int b_r = (lane & 7) + ((lane & 16) ? 8 : 0);
    const int b_c = (lane & 8) ? 8 : 0;
    const uint32_t pa0 = base + (uint32_t)((wrow + a_r) * AST2 + a_c) * 2;

    {
        const int qr = tid >> 1;
        const int qh = (tid & 1) * 32;
        const __half* qsrc = Qb + (size_t)qr * DK + qh;
        const uint32_t qdst = base + (uint32_t)(qr * AST2 + qh) * 2;
#pragma unroll
        for (int c = 0; c < 4; c++) CP_ASYNC16(qdst + c * 16, qsrc + c * 8);
    }
    {
        const __half* ks = Kb + (size_t)ld * DK + lh;
        const uint32_t kd = base + (uint32_t)(A_K0 + ld * AST2 + lh) * 2;
        const __half* vs = Vb + (size_t)ld * SEQ + lh;
        const uint32_t vd = base + (uint32_t)(A_V0 + ld * AST2 + lh) * 2;
        CP_ASYNC16(kd, ks); CP_ASYNC16(kd + 16, ks + 8);
        CP_ASYNC16(vd, vs); CP_ASYNC16(vd + 16, vs + 8);
    }
    CP_COMMIT();
    {
        const __half* ks = Kb + (size_t)(64 + ld) * DK + lh;
        const uint32_t kd = base + (uint32_t)(A_K0 + A_KB + ld * AST2 + lh) * 2;
        const __half* vs = Vb + (size_t)ld * SEQ + 64 + lh;
        const uint32_t vd = base + (uint32_t)(A_V0 + A_VB + ld * AST2 + lh) * 2;
        CP_ASYNC16(kd, ks); CP_ASYNC16(kd + 16, ks + 8);
        CP_ASYNC16(vd, vs); CP_ASYNC16(vd + 16, vs + 8);
    }
    CP_COMMIT();
    CP_WAIT(1);
    __syncthreads();

    uint32_t qa[4][4];
#pragma unroll
    for (int ki = 0; ki < 4; ki++)
        LDSM_X4(qa[ki][0], qa[ki][1], qa[ki][2], qa[ki][3],
                pa0 + (uint32_t)(ki * 16) * 2);

    float m_i[2] = {-1e30f, -1e30f};
    float l_i[2] = {0.0f, 0.0f};
    float acc[8][4];
#pragma unroll
    for (int dt = 0; dt < 8; dt++)
#pragma unroll
        for (int i = 0; i < 4; i++) acc[dt][i] = 0.0f;

    const int NKT = SEQ / 64;
    for (int it = 0; it < NKT; it++) {
        if (it) { CP_WAIT(1); __syncthreads(); }

        const uint32_t kbase = base + (uint32_t)(A_K0 + (it & 1) * A_KB) * 2
                             + (uint32_t)(b_r * AST2 + b_c) * 2;
        const uint32_t vbase = base + (uint32_t)(A_V0 + (it & 1) * A_VB) * 2
                             + (uint32_t)(b_r * AST2 + b_c) * 2;

        float s[8][4];
#pragma unroll
        for (int nt = 0; nt < 8; nt++)
#pragma unroll
            for (int i = 0; i < 4; i++) s[nt][i] = 0.0f;

#pragma unroll
        for (int ki = 0; ki < 4; ki++) {
            const int ko = ki * 16;
            uint32_t kb[8][2];
#pragma unroll
            for (int ntp = 0; ntp < 4; ntp++)
                LDSM_X4(kb[2 * ntp][0], kb[2 * ntp][1],
                        kb[2 * ntp + 1][0], kb[2 * ntp + 1][1],
                        kbase + (uint32_t)(ntp * 16 * AST2 + ko) * 2);
#pragma unroll
            for (int nt = 0; nt < 8; nt++)
                mma_f16(s[nt], qa[ki][0], qa[ki][1], qa[ki][2], qa[ki][3],
                        kb[nt][0], kb[nt][1]);
        }

        float fac[2];
#pragma unroll
        for (int r = 0; r < 2; r++) {
            float mx = -1e30f;
#pragma unroll
            for (int nt = 0; nt < 8; nt++)
                mx = fmaxf(mx, fmaxf(s[nt][2 * r], s[nt][2 * r + 1]));
            mx = fmaxf(mx, __shfl_xor_sync(0xffffffffu, mx, 1));
            mx = fmaxf(mx, __shfl_xor_sync(0xffffffffu, mx, 2));
            const float mn = fmaxf(m_i[r], mx);
            fac[r] = __expf(m_i[r] - mn);
            m_i[r] = mn;
            float ls = 0.0f;
#pragma unroll
            for (int nt = 0; nt < 8; nt++) {
                float p0 = __half2float(__float2half_rn(__expf(s[nt][2 * r + 0] - mn)));
                float p1 = __half2float(__float2half_rn(__expf(s[nt][2 * r + 1] - mn)));
                s[nt][2 * r + 0] = p0;
                s[nt][2 * r + 1] = p1;
                ls += p0 + p1;
            }
            ls += __shfl_xor_sync(0xffffffffu, ls, 1);
            ls += __shfl_xor_sync(0xffffffffu, ls, 2);
            l_i[r] = l_i[r] * fac[r] + ls;
        }

#pragma unroll
        for (int nt = 0; nt < 8; nt++) {
            *(__half2*)(Ps + (wrow + G) * AST2 + nt * 8 + 2 * T) =
                __floats2half2_rn(s[nt][0], s[nt][1]);
            *(__half2*)(Ps + (wrow + G + 8) * AST2 + nt * 8 + 2 * T) =
                __floats2half2_rn(s[nt][2], s[nt][3]);
        }
        __syncwarp();

#pragma unroll
        for (int dt = 0; dt < 8; dt++) {
            acc[dt][0] *= fac[0];
            acc[dt][1] *= fac[0];
            acc[dt][2] *= fac[1];
            acc[dt][3] *= fac[1];
        }

#pragma unroll
        for (int ki = 0; ki < 4; ki++) {
            const int ko = ki * 16;
            uint32_t a0, a1, a2, a3;
            LDSM_X4(a0, a1, a2, a3, pa0 + (uint32_t)ko * 2);
            uint32_t vb[8][2];
#pragma unroll
            for (int dtp = 0; dtp < 4; dtp++)
                LDSM_X4(vb[2 * dtp][0], vb[2 * dtp][1],
                        vb[2 * dtp + 1][0], vb[2 * dtp + 1][1],
                        vbase + (uint32_t)(dtp * 16 * AST2 + ko) * 2);
#pragma unroll
            for (int dt = 0; dt < 8; dt++)
                mma_f16(acc[dt], a0, a1, a2, a3, vb[dt][0], vb[dt][1]);
        }

        __syncthreads();
        if (it + 2 < NKT) {
            const int kt2 = (it + 2) * 64;
            const __half* ks = Kb + (size_t)(kt2 + ld) * DK + lh;
            const uint32_t kd = base + (uint32_t)(A_K0 + (it & 1) * A_KB + ld * AST2 + lh) * 2;
            const __half* vs = Vb + (size_t)ld * SEQ + kt2 + lh;
            const uint32_t vd = base + (uint32_t)(A_V0 + (it & 1) * A_VB + ld * AST2 + lh) * 2;
            CP_ASYNC16(kd, ks); CP_ASYNC16(kd + 16, ks + 8);
            CP_ASYNC16(vd, vs); CP_ASYNC16(vd + 16, vs + 8);
        }
        CP_COMMIT();
    }

    const int b = bh >> 4;
    const int h = bh & 15;
    const float inv0 = 1.0f / l_i[0];
    const float inv1 = 1.0f / l_i[1];
    const int r0 = q0 + wrow + G;
    const int r1 = r0 + 8;
    const size_t o0 = ((size_t)b * SEQ + r0) * DMODEL + h * DK;
    const size_t o1 = ((size_t)b * SEQ + r1) * DMODEL + h * DK;
#pragma unroll
    for (int dt = 0; dt < 8; dt++) {
        const int d = dt * 8 + 2 * T;
        float x0 = acc[dt][0] * inv0, y0 = acc[dt][1] * inv0;
        float x1 = acc[dt][2] * inv1, y1 = acc[dt][3] * inv1;
        __half2 h0, l0, h1, l1;
        __half hh, ll;
        f16_split(x0, hh, ll); h0.x = hh; l0.x = ll;
        f16_split(y0, hh, ll); h0.y = hh; l0.y = ll;
        f16_split(x1, hh, ll); h1.x = hh; l1.x = ll;
        f16_split(y1, hh, ll); h1.y = hh; l1.y = ll;
        *(__half2*)&Ohi[o0 + d] = h0;
        *(__half2*)&Olo[o0 + d] = l0;
        *(__half2*)&Ohi[o1 + d] = h1;
        *(__half2*)&Olo[o1 + d] = l1;
    }
}

// ---------------- launch ----------------
extern "C" void kernel_launch(void* const* d_in, const int* in_sizes, int n_in,
                              void* d_out, int out_size)
{
    const float* x  = (const float*)d_in[0];
    const float* Wq = (const float*)d_in[1];
    const float* bq = (const float*)d_in[2];
    const float* Wk = (const float*)d_in[3];
    const float* bk = (const float*)d_in[4];
    const float* Wv = (const float*)d_in[5];
    const float* bv = (const float*)d_in[6];
    const float* Wo = (const float*)d_in[7];
    const float* bo = (const float*)d_in[8];
    float* out = (float*)d_out;

    __half *gq, *gk, *gv, *gxh, *gxl, *gah, *gal, *wq, *wk, *wv, *wo;
    cudaGetSymbolAddress((void**)&gq,  g_q);
    cudaGetSymbolAddress((void**)&gk,  g_k);
    cudaGetSymbolAddress((void**)&gv,  g_v);
    cudaGetSymbolAddress((void**)&gxh, g_xh);
    cudaGetSymbolAddress((void**)&gxl, g_xl);
    cudaGetSymbolAddress((void**)&gah, g_aoh);
    cudaGetSymbolAddress((void**)&gal, g_aol);
    cudaGetSymbolAddress((void**)&wq,  g_wq);
    cudaGetSymbolAddress((void**)&wk,  g_wk);
    cudaGetSymbolAddress((void**)&wv,  g_wv);
    cudaGetSymbolAddress((void**)&wo,  g_wo);

    cudaFuncSetAttribute(gemm2_f16, cudaFuncAttributeMaxDynamicSharedMemorySize,
                         B_SMEM);
    cudaFuncSetAttribute(attn_mma, cudaFuncAttributeMaxDynamicSharedMemorySize,
                         A_SMEM);

    split_all_kernel<<<(NTASK + 255) / 256, 256>>>(
        x, Wq, Wk, Wv, Wo, gxh, gxl, wq, wk, wv, wo);

    dim3 gqkv(DMODEL / 128, MROWS / 128, 3);
    gemm2_f16<<<gqkv, 256, B_SMEM>>>(gxh, gxl,
                                     wq, bq, gq,
                                     wk, bk, gk,
                                     wv, bv, gv, 1, 2, 3);

    attn_mma<<<dim3(SEQ / 128, BATCH * NHEAD), 256, A_SMEM>>>(gq, gk, gv, gah, gal);

    dim3 go(DMODEL / 128, MROWS / 128, 1);
    gemm2_f16<<<go, 256, B_SMEM>>>(gah, gal,
                                   wo, bo, out,
                                   wo, bo, out,
                                   wo, bo, out, 0, 0, 0);
}

// round 16
// speedup vs baseline: 1.3681x; 1.0425x over previous
#include <cuda_runtime.h>
#include <cuda_fp16.h>
#include <cstdint>
#include <cstddef>

#define BATCH  2
#define SEQ    2048
#define DMODEL 1024
#define NHEAD  16
#define DK     64
#define MROWS  (BATCH * SEQ)
#define KDIM   1024

__device__ __half g_q[BATCH * NHEAD * SEQ * DK];
__device__ __half g_k[BATCH * NHEAD * SEQ * DK];
__device__ __half g_v[BATCH * NHEAD * DK * SEQ];
__device__ __half g_xh[MROWS * DMODEL];
__device__ __half g_xl[MROWS * DMODEL];
__device__ __half g_aoh[MROWS * DMODEL];
__device__ __half g_aol[MROWS * DMODEL];
__device__ __half g_wq[DMODEL * DMODEL];
__device__ __half g_wk[DMODEL * DMODEL];
__device__ __half g_wv[DMODEL * DMODEL];
__device__ __half g_wo[DMODEL * DMODEL];

__device__ __forceinline__ uint32_t smem_u32(const void* p) {
    uint32_t a;
    asm("{ .reg .u64 t; cvta.to.shared.u64 t, %1; cvt.u32.u64 %0, t; }"
        : "=r"(a) : "l"(p));
    return a;
}

__device__ __forceinline__ uint32_t h2u(__half2 h) {
    union { __half2 h2; uint32_t u; } cvt;
    cvt.h2 = h;
    return cvt.u;
}

#define CP_ASYNC16(dst_u32, src_ptr) \
    asm volatile("cp.async.cg.shared.global [%0], [%1], 16;" \
        :: "r"(dst_u32), "l"((const void*)(src_ptr)) : "memory")
#define CP_COMMIT() asm volatile("cp.async.commit_group;" ::: "memory")
#define CP_WAIT(n)  asm volatile("cp.async.wait_group %0;" :: "n"(n) : "memory")

#define LDSM_X4(r0, r1, r2, r3, addr) \
    asm volatile("ldmatrix.sync.aligned.m8n8.x4.shared.b16 {%0,%1,%2,%3}, [%4];" \
        : "=r"(r0), "=r"(r1), "=r"(r2), "=r"(r3) : "r"(addr))

__device__ __forceinline__ void mma_f16(float c[4], uint32_t a0, uint32_t a1,
                                        uint32_t a2, uint32_t a3,
                                        uint32_t b0, uint32_t b1) {
    asm volatile(
        "mma.sync.aligned.m16n8k16.row.col.f32.f16.f16.f32 "
        "{%0,%1,%2,%3}, {%4,%5,%6,%7}, {%8,%9}, {%0,%1,%2,%3};"
        : "+f"(c[0]), "+f"(c[1]), "+f"(c[2]), "+f"(c[3])
        : "r"(a0), "r"(a1), "r"(a2), "r"(a3), "r"(b0), "r"(b1));
}

__device__ __forceinline__ void f16_split(float v, __half& h, __half& l) {
    h = __float2half_rn(v);
    l = __float2half_rn(v - __half2float(h));
}

// ---------------- pre-pass: x -> fp16 hi/lo ; W -> fp16 ----------------
#define NX4 ((MROWS * DMODEL) / 4)
#define NW4 ((DMODEL * DMODEL) / 4)
#define NTASK (NX4 + 4 * NW4)

__global__ void split_all_kernel(
    const float* __restrict__ x,
    const float* __restrict__ Wq, const float* __restrict__ Wk,
    const float* __restrict__ Wv, const float* __restrict__ Wo,
    __half* __restrict__ xh, __half* __restrict__ xl,
    __half* __restrict__ wq, __half* __restrict__ wk,
    __half* __restrict__ wv, __half* __restrict__ wo)
{
    int i = blockIdx.x * blockDim.x + threadIdx.x;
    if (i >= NTASK) return;
    if (i < NX4) {
        float4 v = ((const float4*)x)[i];
        __half2 h0, h1, l0, l1;
        __half h, l;
        f16_split(v.x, h, l); h0.x = h; l0.x = l;
        f16_split(v.y, h, l); h0.y = h; l0.y = l;
        f16_split(v.z, h, l); h1.x = h; l1.x = l;
        f16_split(v.w, h, l); h1.y = h; l1.y = l;
        ((__half2*)xh)[2 * i + 0] = h0;
        ((__half2*)xh)[2 * i + 1] = h1;
        ((__half2*)xl)[2 * i + 0] = l0;
        ((__half2*)xl)[2 * i + 1] = l1;
    } else {
        int j = i - NX4;
        int t = j / NW4;
        int o = j - t * NW4;
        const float* in = (t == 0) ? Wq : (t == 1) ? Wk : (t == 2) ? Wv : Wo;
        __half* oh = (t == 0) ? wq : (t == 1) ? wk : (t == 2) ? wv : wo;
        float4 v = ((const float4*)in)[o];
        ((__half2*)oh)[2 * o + 0] = __floats2half2_rn(v.x, v.y);
        ((__half2*)oh)[2 * o + 1] = __floats2half2_rn(v.z, v.w);
    }
}

// ---------------- 2-term FP16 GEMM, BBK=64 ----------------
#define BBK 64
#define BRS 72
#define B_TILE (128 * BRS)
#define B_STAGE (3 * B_TILE)
#define B_SMEM (2 * B_STAGE * 2)      // 110592 B

__device__ __forceinline__ void gemmb_load(
    const __half* __restrict__ Ah, const __half* __restrict__ Al,
    const __half* __restrict__ Wm,
    int bm, int bn, uint32_t base, int tid, int k0, int s)
{
    const __half* bases[3] = {
        Ah + (size_t)bm * KDIM, Al + (size_t)bm * KDIM,
        Wm + (size_t)bn * KDIM };
    const uint32_t st = base + (uint32_t)(s * B_STAGE) * 2;
#pragma unroll
    for (int i = 0; i < 12; i++) {
        const int task = tid + 256 * i;
        const int t = task >> 10;
        const int rem = task & 1023;
        const int r = rem >> 3;
        const int seg = rem & 7;
        const __half* src = bases[t] + (size_t)r * KDIM + k0 + seg * 8;
        const uint32_t dst = st + (uint32_t)(t * B_TILE + r * BRS + seg * 8) * 2;
        CP_ASYNC16(dst, src);
    }
}

__global__ void __launch_bounds__(256, 2) gemm2_f16(
    const __half* __restrict__ Ah, const __half* __restrict__ Al,
    const __half* __restrict__ W0, const float* __restrict__ b0v,
    void* __restrict__ C0,
    const __half* __restrict__ W1, const float* __restrict__ b1v,
    void* __restrict__ C1,
    const __half* __restrict__ W2, const float* __restrict__ b2v,
    void* __restrict__ C2,
    int m0, int m1, int m2)
{
    extern __shared__ char smem_raw[];
    const uint32_t base = smem_u32(smem_raw);
    const int tid = threadIdx.x;
    const int wid = tid >> 5;
    const int lane = tid & 31;
    const int G = lane >> 2;
    const int T = lane & 3;
    const int wm = (wid >> 2) * 64;
    const int wn = (wid & 3) * 32;
    const int bm = blockIdx.y * 128;
    const int bn = blockIdx.x * 128;
    const int z = blockIdx.z;

    const __half* Wm = (z == 0) ? W0 : (z == 1) ? W1 : W2;
    const float* bias = (z == 0) ? b0v : (z == 1) ? b1v : b2v;
    void* C = (z == 0) ? C0 : (z == 1) ? C1 : C2;
    const int mode = (z == 0) ? m0 : (z == 1) ? m1 : m2;

    const int a_r = lane & 15;
    const int a_c = (lane & 16) ? 8 : 0;
    const int b_r = (lane & 7) + ((lane & 16) ? 8 : 0);
    const int b_c = (lane & 8) ? 8 : 0;
    const uint32_t a_addr0 = base + (uint32_t)((wm + a_r) * BRS + a_c) * 2;
    const uint32_t b_addr0 = base + (uint32_t)((wn + b_r) * BRS + b_c) * 2
                           + (uint32_t)(2 * B_TILE) * 2;

    float c[4][4][4];
#pragma unroll
    for (int mt = 0; mt < 4; mt++)
#pragma unroll
        for (int nt = 0; nt < 4; nt++)
#pragma unroll
            for (int i = 0; i < 4; i++) c[mt][nt][i] = 0.0f;

    gemmb_load(Ah, Al, Wm, bm, bn, base, tid, 0, 0);
    CP_COMMIT();

    const int NIT = KDIM / BBK;   // 16
    for (int k = 0; k < NIT; k++) {
        if (k + 1 < NIT) {
            gemmb_load(Ah, Al, Wm, bm, bn, base, tid, (k + 1) * BBK, (k + 1) & 1);
            CP_COMMIT();
            CP_WAIT(1);
        } else {
            CP_WAIT(0);
        }
        __syncthreads();

        const uint32_t sb = (uint32_t)((k & 1) * B_STAGE) * 2;
        const uint32_t tile2 = (uint32_t)B_TILE * 2;

#pragma unroll
        for (int ko = 0; ko < BBK; ko += 16) {
            uint32_t bw[4][2];
#pragma unroll
            for (int ntp = 0; ntp < 2; ntp++) {
                const uint32_t ba = b_addr0 + sb + (uint32_t)(ntp * 16 * BRS + ko) * 2;
                LDSM_X4(bw[2 * ntp][0], bw[2 * ntp][1],
                        bw[2 * ntp + 1][0], bw[2 * ntp + 1][1], ba);
            }
#pragma unroll
            for (int mt = 0; mt < 4; mt++) {
                const uint32_t aa = a_addr0 + sb + (uint32_t)(mt * 16 * BRS + ko) * 2;
                uint32_t ah0, ah1, ah2, ah3, al0, al1, al2, al3;
                LDSM_X4(ah0, ah1, ah2, ah3, aa);
                LDSM_X4(al0, al1, al2, al3, aa + tile2);
#pragma unroll
                for (int nt = 0; nt < 4; nt++)
                    mma_f16(c[mt][nt], ah0, ah1, ah2, ah3, bw[nt][0], bw[nt][1]);
#pragma unroll
                for (int nt = 0; nt < 4; nt++)
                    mma_f16(c[mt][nt], al0, al1, al2, al3, bw[nt][0], bw[nt][1]);
            }
        }
        __syncthreads();
    }

#pragma unroll
    for (int mt = 0; mt < 4; mt++) {
#pragma unroll
        for (int half = 0; half < 2; half++) {
            const int gm = bm + wm + mt * 16 + G + half * 8;
            const int b_ = gm >> 11;
            const int s_ = gm & 2047;
#pragma unroll
            for (int nt = 0; nt < 4; nt++) {
                const int gn = bn + wn + nt * 8 + 2 * T;
                float2 bv = *(const float2*)&bias[gn];
                float vx = c[mt][nt][half * 2 + 0] + bv.x;
                float vy = c[mt][nt][half * 2 + 1] + bv.y;
                const int h = gn >> 6, d = gn & 63;
                if (mode == 0) {
                    float2 v; v.x = vx; v.y = vy;
                    *(float2*)((float*)C + (size_t)gm * DMODEL + gn) = v;
                } else if (mode == 1) {
                    __half2 v = __floats2half2_rn(vx * 0.125f, vy * 0.125f);
                    *(__half2*)((__half*)C + (((size_t)(b_ * NHEAD + h) * SEQ) + s_) * DK + d) = v;
                } else if (mode == 2) {
                    __half2 v = __floats2half2_rn(vx, vy);
                    *(__half2*)((__half*)C + (((size_t)(b_ * NHEAD + h) * SEQ) + s_) * DK + d) = v;
                } else {
                    __half* Cb = (__half*)C + ((size_t)(b_ * NHEAD + h) * DK + d) * SEQ + s_;
                    Cb[0]   = __float2half_rn(vx);
                    Cb[SEQ] = __float2half_rn(vy);
                }
            }
        }
    }
}

// ---------------- FP16 mma flash attention: P stays in registers ------------
#define AST2 72
#define A_PS 0
#define A_K0 (128 * AST2)
#define A_KB (64 * AST2)
#define A_V0 (A_K0 + 2 * A_KB)
#define A_VB (64 * AST2)
#define A_SMEM ((A_V0 + 2 * A_VB) * 2)   // 55296 B

__global__ void __launch_bounds__(256, 2) attn_mma(
    const __half* __restrict__ Qg, const __half* __restrict__ Kg,
    const __half* __restrict__ Vg, __half* __restrict__ Ohi,
    __half* __restrict__ Olo)
{
    extern __shared__ __half sh[];
    const uint32_t base = smem_u32(sh);

    const int tid = threadIdx.x;
    const int w = tid >> 5;
    const int lane = tid & 31;
    const int G = lane >> 2;
    const int T = lane & 3;
    const int bh = blockIdx.y;
    const int q0 = blockIdx.x * 128;
    const int wrow = w * 16;

    const __half* Qb = Qg + ((size_t)bh * SEQ + q0) * DK;
    const __half* Kb = Kg + (size_t)bh * SEQ * DK;
    const __half* Vb = Vg + (size_t)bh * DK * SEQ;

    const int ld = tid >> 2;
    const int lh = (tid & 3) * 16;

    const int a_r = lane & 15;
    const int a_c = (lane & 16) ? 8 : 0;
    const int b_r = (lane & 7) + ((lane & 16) ? 8 : 0);
    const int b_c = (lane & 8) ? 8 : 0;
    const uint32_t pa0 = base + (uint32_t)((wrow + a_r) * AST2 + a_c) * 2;

    // prologue: Q (staged in the A_PS region) + KV tile0 | KV tile1
    {
        const int qr = tid >> 1;
        const int qh = (tid & 1) * 32;
        const __half* qsrc = Qb + (size_t)qr * DK + qh;
        const uint32_t qdst = base + (uint32_t)(qr * AST2 + qh) * 2;
#pragma unroll
        for (int c = 0; c < 4; c++) CP_ASYNC16(qdst + c * 16, qsrc + c * 8);
    }
    {
        const __half* ks = Kb + (size_t)ld * DK + lh;
        const uint32_t kd = base + (uint32_t)(A_K0 + ld * AST2 + lh) * 2;
        const __half* vs = Vb + (size_t)ld * SEQ + lh;
        const uint32_t vd = base + (uint32_t)(A_V0 + ld * AST2 + lh) * 2;
        CP_ASYNC16(kd, ks); CP_ASYNC16(kd + 16, ks + 8);
        CP_ASYNC16(vd, vs); CP_ASYNC16(vd + 16, vs + 8);
    }
    CP_COMMIT();
    {
        const __half* ks = Kb + (size_t)(64 + ld) * DK + lh;
        const uint32_t kd = base + (uint32_t)(A_K0 + A_KB + ld * AST2 + lh) * 2;
        const __half* vs = Vb + (size_t)ld * SEQ + 64 + lh;
        const uint32_t vd = base + (uint32_t)(A_V0 + A_VB + ld * AST2 + lh) * 2;
        CP_ASYNC16(kd, ks); CP_ASYNC16(kd + 16, ks + 8);
        CP_ASYNC16(vd, vs); CP_ASYNC16(vd + 16, vs + 8);
    }
    CP_COMMIT();
    CP_WAIT(1);
    __syncthreads();

    uint32_t qa[4][4];
#pragma unroll
    for (int ki = 0; ki < 4; ki++)
        LDSM_X4(qa[ki][0], qa[ki][1], qa[ki][2], qa[ki][3],
                pa0 + (uint32_t)(ki * 16) * 2);

    float m_i[2] = {-1e30f, -1e30f};
    float l_i[2] = {0.0f, 0.0f};
    float acc[8][4];
#pragma unroll
    for (int dt = 0; dt < 8; dt++)
#pragma unroll
        for (int i = 0; i < 4; i++) acc[dt][i] = 0.0f;

    const int NKT = SEQ / 64;
    for (int it = 0; it < NKT; it++) {
        if (it) { CP_WAIT(1); __syncthreads(); }

        const uint32_t kbase = base + (uint32_t)(A_K0 + (it & 1) * A_KB) * 2
                             + (uint32_t)(b_r * AST2 + b_c) * 2;
        const uint32_t vbase = base + (uint32_t)(A_V0 + (it & 1) * A_VB) * 2
                             + (uint32_t)(b_r * AST2 + b_c) * 2;

        // ---- QK^T
        float s[8][4];
#pragma unroll
        for (int nt = 0; nt < 8; nt++)
#pragma unroll
            for (int i = 0; i < 4; i++) s[nt][i] = 0.0f;

#pragma unroll
        for (int ki = 0; ki < 4; ki++) {
            const int ko = ki * 16;
            uint32_t kb[8][2];
#pragma unroll
            for (int ntp = 0; ntp < 4; ntp++)
                LDSM_X4(kb[2 * ntp][0], kb[2 * ntp][1],
                        kb[2 * ntp + 1][0], kb[2 * ntp + 1][1],
                        kbase + (uint32_t)(ntp * 16 * AST2 + ko) * 2);
#pragma unroll
            for (int nt = 0; nt < 8; nt++)
                mma_f16(s[nt], qa[ki][0], qa[ki][1], qa[ki][2], qa[ki][3],
                        kb[nt][0], kb[nt][1]);
        }

        // ---- online softmax (fp16-rounded P kept in registers)
        float fac[2];
#pragma unroll
        for (int r = 0; r < 2; r++) {
            float mx = -1e30f;
#pragma unroll
            for (int nt = 0; nt < 8; nt++)
                mx = fmaxf(mx, fmaxf(s[nt][2 * r], s[nt][2 * r + 1]));
            mx = fmaxf(mx, __shfl_xor_sync(0xffffffffu, mx, 1));
            mx = fmaxf(mx, __shfl_xor_sync(0xffffffffu, mx, 2));
            const float mn = fmaxf(m_i[r], mx);
            fac[r] = __expf(m_i[r] - mn);
            m_i[r] = mn;
            float ls = 0.0f;
#pragma unroll
            for (int nt = 0; nt < 8; nt++) {
                float p0 = __half2float(__float2half_rn(__expf(s[nt][2 * r + 0] - mn)));
                float p1 = __half2float(__float2half_rn(__expf(s[nt][2 * r + 1] - mn)));
                s[nt][2 * r + 0] = p0;
                s[nt][2 * r + 1] = p1;
                ls += p0 + p1;
            }
            ls += __shfl_xor_sync(0xffffffffu, ls, 1);
            ls += __shfl_xor_sync(0xffffffffu, ls, 2);
            l_i[r] = l_i[r] * fac[r] + ls;
        }

        // ---- rescale accumulators
#pragma unroll
        for (int dt = 0; dt < 8; dt++) {
            acc[dt][0] *= fac[0];
            acc[dt][1] *= fac[0];
            acc[dt][2] *= fac[1];
            acc[dt][3] *= fac[1];
        }

        // ---- PV: A-fragments packed directly from s (no smem round-trip)
#pragma unroll
        for (int ki = 0; ki < 4; ki++) {
            const int ko = ki * 16;
            uint32_t a0 = h2u(__floats2half2_rn(s[2 * ki][0], s[2 * ki][1]));
            uint32_t a1 = h2u(__floats2half2_rn(s[2 * ki][2], s[2 * ki][3]));
            uint32_t a2 = h2u(__floats2half2_rn(s[2 * ki + 1][0], s[2 * ki + 1][1]));
            uint32_t a3 = h2u(__floats2half2_rn(s[2 * ki + 1][2], s[2 * ki + 1][3]));
            uint32_t vb[8][2];
#pragma unroll
            for (int dtp = 0; dtp < 4; dtp++)
                LDSM_X4(vb[2 * dtp][0], vb[2 * dtp][1],
                        vb[2 * dtp + 1][0], vb[2 * dtp + 1][1],
                        vbase + (uint32_t)(dtp * 16 * AST2 + ko) * 2);
#pragma unroll
            for (int dt = 0; dt < 8; dt++)
                mma_f16(acc[dt], a0, a1, a2, a3, vb[dt][0], vb[dt][1]);
        }

        __syncthreads();
        if (it + 2 < NKT) {
            const int kt2 = (it + 2) * 64;
            const __half* ks = Kb + (size_t)(kt2 + ld) * DK + lh;
            const uint32_t kd = base + (uint32_t)(A_K0 + (it & 1) * A_KB + ld * AST2 + lh) * 2;
            const __half* vs = Vb + (size_t)ld * SEQ + kt2 + lh;
            const uint32_t vd = base + (uint32_t)(A_V0 + (it & 1) * A_VB + ld * AST2 + lh) * 2;
            CP_ASYNC16(kd, ks); CP_ASYNC16(kd + 16, ks + 8);
            CP_ASYNC16(vd, vs); CP_ASYNC16(vd + 16, vs + 8);
        }
        CP_COMMIT();
    }

    // ---- epilogue: normalize, fp16 hi/lo split
    const int b = bh >> 4;
    const int h = bh & 15;
    const float inv0 = 1.0f / l_i[0];
    const float inv1 = 1.0f / l_i[1];
    const int r0 = q0 + wrow + G;
    const int r1 = r0 + 8;
    const size_t o0 = ((size_t)b * SEQ + r0) * DMODEL + h * DK;
    const size_t o1 = ((size_t)b * SEQ + r1) * DMODEL + h * DK;
#pragma unroll
    for (int dt = 0; dt < 8; dt++) {
        const int d = dt * 8 + 2 * T;
        float x0 = acc[dt][0] * inv0, y0 = acc[dt][1] * inv0;
        float x1 = acc[dt][2] * inv1, y1 = acc[dt][3] * inv1;
        __half2 h0, l0, h1, l1;
        __half hh, ll;
        f16_split(x0, hh, ll); h0.x = hh; l0.x = ll;
        f16_split(y0, hh, ll); h0.y = hh; l0.y = ll;
        f16_split(x1, hh, ll); h1.x = hh; l1.x = ll;
        f16_split(y1, hh, ll); h1.y = hh; l1.y = ll;
        *(__half2*)&Ohi[o0 + d] = h0;
        *(__half2*)&Olo[o0 + d] = l0;
        *(__half2*)&Ohi[o1 + d] = h1;
        *(__half2*)&Olo[o1 + d] = l1;
    }
}

// ---------------- launch ----------------
extern "C" void kernel_launch(void* const* d_in, const int* in_sizes, int n_in,
                              void* d_out, int out_size)
{
    const float* x  = (const float*)d_in[0];
    const float* Wq = (const float*)d_in[1];
    const float* bq = (const float*)d_in[2];
    const float* Wk = (const float*)d_in[3];
    const float* bk = (const float*)d_in[4];
    const float* Wv = (const float*)d_in[5];
    const float* bv = (const float*)d_in[6];
    const float* Wo = (const float*)d_in[7];
    const float* bo = (const float*)d_in[8];
    float* out = (float*)d_out;

    __half *gq, *gk, *gv, *gxh, *gxl, *gah, *gal, *wq, *wk, *wv, *wo;
    cudaGetSymbolAddress((void**)&gq,  g_q);
    cudaGetSymbolAddress((void**)&gk,  g_k);
    cudaGetSymbolAddress((void**)&gv,  g_v);
    cudaGetSymbolAddress((void**)&gxh, g_xh);
    cudaGetSymbolAddress((void**)&gxl, g_xl);
    cudaGetSymbolAddress((void**)&gah, g_aoh);
    cudaGetSymbolAddress((void**)&gal, g_aol);
    cudaGetSymbolAddress((void**)&wq,  g_wq);
    cudaGetSymbolAddress((void**)&wk,  g_wk);
    cudaGetSymbolAddress((void**)&wv,  g_wv);
    cudaGetSymbolAddress((void**)&wo,  g_wo);

    cudaFuncSetAttribute(gemm2_f16, cudaFuncAttributeMaxDynamicSharedMemorySize,
                         B_SMEM);
    cudaFuncSetAttribute(attn_mma, cudaFuncAttributeMaxDynamicSharedMemorySize,
                         A_SMEM);

    split_all_kernel<<<(NTASK + 255) / 256, 256>>>(
        x, Wq, Wk, Wv, Wo, gxh, gxl, wq, wk, wv, wo);

    dim3 gqkv(DMODEL / 128, MROWS / 128, 3);
    gemm2_f16<<<gqkv, 256, B_SMEM>>>(gxh, gxl,
                                     wq, bq, gq,
                                     wk, bk, gk,
                                     wv, bv, gv, 1, 2, 3);

    attn_mma<<<dim3(SEQ / 128, BATCH * NHEAD), 256, A_SMEM>>>(gq, gk, gv, gah, gal);

    dim3 go(DMODEL / 128, MROWS / 128, 1);
    gemm2_f16<<<go, 256, B_SMEM>>>(gah, gal,
                                   wo, bo, out,
                                   wo, bo, out,
                                   wo, bo, out, 0, 0, 0);
}

// round 17
// speedup vs baseline: 1.3810x; 1.0095x over previous
#include <cuda_runtime.h>
#include <cuda_fp16.h>
#include <cstdint>
#include <cstddef>

#define BATCH  2
#define SEQ    2048
#define DMODEL 1024
#define NHEAD  16
#define DK     64
#define MROWS  (BATCH * SEQ)
#define KDIM   1024
#define QSCALE 0.18033688011112042f   // 0.125 * log2(e)

__device__ __half g_q[BATCH * NHEAD * SEQ * DK];
__device__ __half g_k[BATCH * NHEAD * SEQ * DK];
__device__ __half g_v[BATCH * NHEAD * DK * SEQ];
__device__ __half g_xh[MROWS * DMODEL];
__device__ __half g_xl[MROWS * DMODEL];
__device__ __half g_aoh[MROWS * DMODEL];
__device__ __half g_aol[MROWS * DMODEL];
__device__ __half g_wq[DMODEL * DMODEL];
__device__ __half g_wk[DMODEL * DMODEL];
__device__ __half g_wv[DMODEL * DMODEL];
__device__ __half g_wo[DMODEL * DMODEL];

__device__ __forceinline__ uint32_t smem_u32(const void* p) {
    uint32_t a;
    asm("{ .reg .u64 t; cvta.to.shared.u64 t, %1; cvt.u32.u64 %0, t; }"
        : "=r"(a) : "l"(p));
    return a;
}

__device__ __forceinline__ uint32_t h2u(__half2 h) {
    union { __half2 h2; uint32_t u; } cvt;
    cvt.h2 = h;
    return cvt.u;
}

#define CP_ASYNC16(dst_u32, src_ptr) \
    asm volatile("cp.async.cg.shared.global [%0], [%1], 16;" \
        :: "r"(dst_u32), "l"((const void*)(src_ptr)) : "memory")
#define CP_COMMIT() asm volatile("cp.async.commit_group;" ::: "memory")
#define CP_WAIT(n)  asm volatile("cp.async.wait_group %0;" :: "n"(n) : "memory")

#define LDSM_X4(r0, r1, r2, r3, addr) \
    asm volatile("ldmatrix.sync.aligned.m8n8.x4.shared.b16 {%0,%1,%2,%3}, [%4];" \
        : "=r"(r0), "=r"(r1), "=r"(r2), "=r"(r3) : "r"(addr))

__device__ __forceinline__ void mma_f16(float c[4], uint32_t a0, uint32_t a1,
                                        uint32_t a2, uint32_t a3,
                                        uint32_t b0, uint32_t b1) {
    asm volatile(
        "mma.sync.aligned.m16n8k16.row.col.f32.f16.f16.f32 "
        "{%0,%1,%2,%3}, {%4,%5,%6,%7}, {%8,%9}, {%0,%1,%2,%3};"
        : "+f"(c[0]), "+f"(c[1]), "+f"(c[2]), "+f"(c[3])
        : "r"(a0), "r"(a1), "r"(a2), "r"(a3), "r"(b0), "r"(b1));
}

__device__ __forceinline__ void f16_split(float v, __half& h, __half& l) {
    h = __float2half_rn(v);
    l = __float2half_rn(v - __half2float(h));
}

// ---------------- pre-pass: x -> fp16 hi/lo ; W -> fp16 ----------------
#define NX4 ((MROWS * DMODEL) / 4)
#define NW4 ((DMODEL * DMODEL) / 4)
#define NTASK (NX4 + 4 * NW4)

__global__ void split_all_kernel(
    const float* __restrict__ x,
    const float* __restrict__ Wq, const float* __restrict__ Wk,
    const float* __restrict__ Wv, const float* __restrict__ Wo,
    __half* __restrict__ xh, __half* __restrict__ xl,
    __half* __restrict__ wq, __half* __restrict__ wk,
    __half* __restrict__ wv, __half* __restrict__ wo)
{
    int i = blockIdx.x * blockDim.x + threadIdx.x;
    if (i >= NTASK) return;
    if (i < NX4) {
        float4 v = ((const float4*)x)[i];
        __half2 h0, h1, l0, l1;
        __half h, l;
        f16_split(v.x, h, l); h0.x = h; l0.x = l;
        f16_split(v.y, h, l); h0.y = h; l0.y = l;
        f16_split(v.z, h, l); h1.x = h; l1.x = l;
        f16_split(v.w, h, l); h1.y = h; l1.y = l;
        ((__half2*)xh)[2 * i + 0] = h0;
        ((__half2*)xh)[2 * i + 1] = h1;
        ((__half2*)xl)[2 * i + 0] = l0;
        ((__half2*)xl)[2 * i + 1] = l1;
    } else {
        int j = i - NX4;
        int t = j / NW4;
        int o = j - t * NW4;
        const float* in = (t == 0) ? Wq : (t == 1) ? Wk : (t == 2) ? Wv : Wo;
        __half* oh = (t == 0) ? wq : (t == 1) ? wk : (t == 2) ? wv : wo;
        float4 v = ((const float4*)in)[o];
        ((__half2*)oh)[2 * o + 0] = __floats2half2_rn(v.x, v.y);
        ((__half2*)oh)[2 * o + 1] = __floats2half2_rn(v.z, v.w);
    }
}

// ---------------- 2-term FP16 GEMM, BBK=64 ----------------
#define BBK 64
#define BRS 72
#define B_TILE (128 * BRS)
#define B_STAGE (3 * B_TILE)
#define B_SMEM (2 * B_STAGE * 2)      // 110592 B

__device__ __forceinline__ void gemmb_load(
    const __half* __restrict__ Ah, const __half* __restrict__ Al,
    const __half* __restrict__ Wm,
    int bm, int bn, uint32_t base, int tid, int k0, int s)
{
    const __half* bases[3] = {
        Ah + (size_t)bm * KDIM, Al + (size_t)bm * KDIM,
        Wm + (size_t)bn * KDIM };
    const uint32_t st = base + (uint32_t)(s * B_STAGE) * 2;
#pragma unroll
    for (int i = 0; i < 12; i++) {
        const int task = tid + 256 * i;
        const int t = task >> 10;
        const int rem = task & 1023;
        const int r = rem >> 3;
        const int seg = rem & 7;
        const __half* src = bases[t] + (size_t)r * KDIM + k0 + seg * 8;
        const uint32_t dst = st + (uint32_t)(t * B_TILE + r * BRS + seg * 8) * 2;
        CP_ASYNC16(dst, src);
    }
}

__global__ void __launch_bounds__(256, 2) gemm2_f16(
    const __half* __restrict__ Ah, const __half* __restrict__ Al,
    const __half* __restrict__ W0, const float* __restrict__ b0v,
    void* __restrict__ C0,
    const __half* __restrict__ W1, const float* __restrict__ b1v,
    void* __restrict__ C1,
    const __half* __restrict__ W2, const float* __restrict__ b2v,
    void* __restrict__ C2,
    int m0, int m1, int m2)
{
    extern __shared__ char smem_raw[];
    const uint32_t base = smem_u32(smem_raw);
    const int tid = threadIdx.x;
    const int wid = tid >> 5;
    const int lane = tid & 31;
    const int G = lane >> 2;
    const int T = lane & 3;
    const int wm = (wid >> 2) * 64;
    const int wn = (wid & 3) * 32;
    const int bm = blockIdx.y * 128;
    const int bn = blockIdx.x * 128;
    const int z = blockIdx.z;

    const __half* Wm = (z == 0) ? W0 : (z == 1) ? W1 : W2;
    const float* bias = (z == 0) ? b0v : (z == 1) ? b1v : b2v;
    void* C = (z == 0) ? C0 : (z == 1) ? C1 : C2;
    const int mode = (z == 0) ? m0 : (z == 1) ? m1 : m2;

    const int a_r = lane & 15;
    const int a_c = (lane & 16) ? 8 : 0;
    const int b_r = (lane & 7) + ((lane & 16) ? 8 : 0);
    const int b_c = (lane & 8) ? 8 : 0;
    const uint32_t a_addr0 = base + (uint32_t)((wm + a_r) * BRS + a_c) * 2;
    const uint32_t b_addr0 = base + (uint32_t)((wn + b_r) * BRS + b_c) * 2
                           + (uint32_t)(2 * B_TILE) * 2;

    float c[4][4][4];
#pragma unroll
    for (int mt = 0; mt < 4; mt++)
#pragma unroll
        for (int nt = 0; nt < 4; nt++)
#pragma unroll
            for (int i = 0; i < 4; i++) c[mt][nt][i] = 0.0f;

    gemmb_load(Ah, Al, Wm, bm, bn, base, tid, 0, 0);
    CP_COMMIT();

    const int NIT = KDIM / BBK;   // 16
    for (int k = 0; k < NIT; k++) {
        if (k + 1 < NIT) {
            gemmb_load(Ah, Al, Wm, bm, bn, base, tid, (k + 1) * BBK, (k + 1) & 1);
            CP_COMMIT();
            CP_WAIT(1);
        } else {
            CP_WAIT(0);
        }
        __syncthreads();

        const uint32_t sb = (uint32_t)((k & 1) * B_STAGE) * 2;
        const uint32_t tile2 = (uint32_t)B_TILE * 2;

#pragma unroll
        for (int ko = 0; ko < BBK; ko += 16) {
            uint32_t bw[4][2];
#pragma unroll
            for (int ntp = 0; ntp < 2; ntp++) {
                const uint32_t ba = b_addr0 + sb + (uint32_t)(ntp * 16 * BRS + ko) * 2;
                LDSM_X4(bw[2 * ntp][0], bw[2 * ntp][1],
                        bw[2 * ntp + 1][0], bw[2 * ntp + 1][1], ba);
            }
#pragma unroll
            for (int mt = 0; mt < 4; mt++) {
                const uint32_t aa = a_addr0 + sb + (uint32_t)(mt * 16 * BRS + ko) * 2;
                uint32_t ah0, ah1, ah2, ah3, al0, al1, al2, al3;
                LDSM_X4(ah0, ah1, ah2, ah3, aa);
                LDSM_X4(al0, al1, al2, al3, aa + tile2);
#pragma unroll
                for (int nt = 0; nt < 4; nt++)
                    mma_f16(c[mt][nt], ah0, ah1, ah2, ah3, bw[nt][0], bw[nt][1]);
#pragma unroll
                for (int nt = 0; nt < 4; nt++)
                    mma_f16(c[mt][nt], al0, al1, al2, al3, bw[nt][0], bw[nt][1]);
            }
        }
        __syncthreads();
    }

#pragma unroll
    for (int mt = 0; mt < 4; mt++) {
#pragma unroll
        for (int half = 0; half < 2; half++) {
            const int gm = bm + wm + mt * 16 + G + half * 8;
            const int b_ = gm >> 11;
            const int s_ = gm & 2047;
#pragma unroll
            for (int nt = 0; nt < 4; nt++) {
                const int gn = bn + wn + nt * 8 + 2 * T;
                float2 bv = *(const float2*)&bias[gn];
                float vx = c[mt][nt][half * 2 + 0] + bv.x;
                float vy = c[mt][nt][half * 2 + 1] + bv.y;
                const int h = gn >> 6, d = gn & 63;
                if (mode == 0) {
                    float2 v; v.x = vx; v.y = vy;
                    *(float2*)((float*)C + (size_t)gm * DMODEL + gn) = v;
                } else if (mode == 1) {
                    __half2 v = __floats2half2_rn(vx * QSCALE, vy * QSCALE);
                    *(__half2*)((__half*)C + (((size_t)(b_ * NHEAD + h) * SEQ) + s_) * DK + d) = v;
                } else if (mode == 2) {
                    __half2 v = __floats2half2_rn(vx, vy);
                    *(__half2*)((__half*)C + (((size_t)(b_ * NHEAD + h) * SEQ) + s_) * DK + d) = v;
                } else {
                    __half* Cb = (__half*)C + ((size_t)(b_ * NHEAD + h) * DK + d) * SEQ + s_;
                    Cb[0]   = __float2half_rn(vx);
                    Cb[SEQ] = __float2half_rn(vy);
                }
            }
        }
    }
}

// ---------------- FP16 mma flash attention: packed-fp16 exp2 softmax --------
// Scores arrive in log2 domain (Q pre-scaled by 0.125*log2e).
#define AST2 72
#define A_PS 0
#define A_K0 (128 * AST2)
#define A_KB (64 * AST2)
#define A_V0 (A_K0 + 2 * A_KB)
#define A_VB (64 * AST2)
#define A_SMEM ((A_V0 + 2 * A_VB) * 2)   // 55296 B

__global__ void __launch_bounds__(256, 2) attn_mma(
    const __half* __restrict__ Qg, const __half* __restrict__ Kg,
    const __half* __restrict__ Vg, __half* __restrict__ Ohi,
    __half* __restrict__ Olo)
{
    extern __shared__ __half sh[];
    const uint32_t base = smem_u32(sh);

    const int tid = threadIdx.x;
    const int w = tid >> 5;
    const int lane = tid & 31;
    const int G = lane >> 2;
    const int T = lane & 3;
    const int bh = blockIdx.y;
    const int q0 = blockIdx.x * 128;
    const int wrow = w * 16;

    const __half* Qb = Qg + ((size_t)bh * SEQ + q0) * DK;
    const __half* Kb = Kg + (size_t)bh * SEQ * DK;
    const __half* Vb = Vg + (size_t)bh * DK * SEQ;

    const int ld = tid >> 2;
    const int lh = (tid & 3) * 16;

    const int a_r = lane & 15;
    const int a_c = (lane & 16) ? 8 : 0;
    const int b_r = (lane & 7) + ((lane & 16) ? 8 : 0);
    const int b_c = (lane & 8) ? 8 : 0;
    const uint32_t pa0 = base + (uint32_t)((wrow + a_r) * AST2 + a_c) * 2;

    // prologue: Q + KV tile0 | KV tile1
    {
        const int qr = tid >> 1;
        const int qh = (tid & 1) * 32;
        const __half* qsrc = Qb + (size_t)qr * DK + qh;
        const uint32_t qdst = base + (uint32_t)(qr * AST2 + qh) * 2;
#pragma unroll
        for (int c = 0; c < 4; c++) CP_ASYNC16(qdst + c * 16, qsrc + c * 8);
    }
    {
        const __half* ks = Kb + (size_t)ld * DK + lh;
        const uint32_t kd = base + (uint32_t)(A_K0 + ld * AST2 + lh) * 2;
        const __half* vs = Vb + (size_t)ld * SEQ + lh;
        const uint32_t vd = base + (uint32_t)(A_V0 + ld * AST2 + lh) * 2;
        CP_ASYNC16(kd, ks); CP_ASYNC16(kd + 16, ks + 8);
        CP_ASYNC16(vd, vs); CP_ASYNC16(vd + 16, vs + 8);
    }
    CP_COMMIT();
    {
        const __half* ks = Kb + (size_t)(64 + ld) * DK + lh;
        const uint32_t kd = base + (uint32_t)(A_K0 + A_KB + ld * AST2 + lh) * 2;
        const __half* vs = Vb + (size_t)ld * SEQ + 64 + lh;
        const uint32_t vd = base + (uint32_t)(A_V0 + A_VB + ld * AST2 + lh) * 2;
        CP_ASYNC16(kd, ks); CP_ASYNC16(kd + 16, ks + 8);
        CP_ASYNC16(vd, vs); CP_ASYNC16(vd + 16, vs + 8);
    }
    CP_COMMIT();
    CP_WAIT(1);
    __syncthreads();

    uint32_t qa[4][4];
#pragma unroll
    for (int ki = 0; ki < 4; ki++)
        LDSM_X4(qa[ki][0], qa[ki][1], qa[ki][2], qa[ki][3],
                pa0 + (uint32_t)(ki * 16) * 2);

    float m_i[2] = {-1e30f, -1e30f};
    float l_i[2] = {0.0f, 0.0f};
    float acc[8][4];
#pragma unroll
    for (int dt = 0; dt < 8; dt++)
#pragma unroll
        for (int i = 0; i < 4; i++) acc[dt][i] = 0.0f;

    const int NKT = SEQ / 64;
    for (int it = 0; it < NKT; it++) {
        if (it) { CP_WAIT(1); __syncthreads(); }

        const uint32_t kbase = base + (uint32_t)(A_K0 + (it & 1) * A_KB) * 2
                             + (uint32_t)(b_r * AST2 + b_c) * 2;
        const uint32_t vbase = base + (uint32_t)(A_V0 + (it & 1) * A_VB) * 2
                             + (uint32_t)(b_r * AST2 + b_c) * 2;

        // ---- QK^T (log2-domain scores)
        float s[8][4];
#pragma unroll
        for (int nt = 0; nt < 8; nt++)
#pragma unroll
            for (int i = 0; i < 4; i++) s[nt][i] = 0.0f;

#pragma unroll
        for (int ki = 0; ki < 4; ki++) {
            const int ko = ki * 16;
            uint32_t kb[8][2];
#pragma unroll
            for (int ntp = 0; ntp < 4; ntp++)
                LDSM_X4(kb[2 * ntp][0], kb[2 * ntp][1],
                        kb[2 * ntp + 1][0], kb[2 * ntp + 1][1],
                        kbase + (uint32_t)(ntp * 16 * AST2 + ko) * 2);
#pragma unroll
            for (int nt = 0; nt < 8; nt++)
                mma_f16(s[nt], qa[ki][0], qa[ki][1], qa[ki][2], qa[ki][3],
                        kb[nt][0], kb[nt][1]);
        }

        // ---- online softmax: packed fp16 exp2, P kept as mma fragments
        float fac[2];
        uint32_t pk[8][2];
#pragma unroll
        for (int r = 0; r < 2; r++) {
            float mx = -1e30f;
#pragma unroll
            for (int nt = 0; nt < 8; nt++)
                mx = fmaxf(mx, fmaxf(s[nt][2 * r], s[nt][2 * r + 1]));
            mx = fmaxf(mx, __shfl_xor_sync(0xffffffffu, mx, 1));
            mx = fmaxf(mx, __shfl_xor_sync(0xffffffffu, mx, 2));
            const float mn = fmaxf(m_i[r], mx);
            fac[r] = exp2f(m_i[r] - mn);
            m_i[r] = mn;
            float ls = 0.0f;
#pragma unroll
            for (int nt = 0; nt < 8; nt++) {
                __half2 xa = __floats2half2_rn(s[nt][2 * r + 0] - mn,
                                               s[nt][2 * r + 1] - mn);
                __half2 pa = h2exp2(xa);
                pk[nt][r] = h2u(pa);
                float2 pf = __half22float2(pa);
                ls += pf.x + pf.y;
            }
            ls += __shfl_xor_sync(0xffffffffu, ls, 1);
            ls += __shfl_xor_sync(0xffffffffu, ls, 2);
            l_i[r] = l_i[r] * fac[r] + ls;
        }

        // ---- rescale accumulators
#pragma unroll
        for (int dt = 0; dt < 8; dt++) {
            acc[dt][0] *= fac[0];
            acc[dt][1] *= fac[0];
            acc[dt][2] *= fac[1];
            acc[dt][3] *= fac[1];
        }

        // ---- PV: fragments already packed in pk
#pragma unroll
        for (int ki = 0; ki < 4; ki++) {
            const int ko = ki * 16;
            uint32_t a0 = pk[2 * ki][0];
            uint32_t a1 = pk[2 * ki][1];
            uint32_t a2 = pk[2 * ki + 1][0];
            uint32_t a3 = pk[2 * ki + 1][1];
            uint32_t vb[8][2];
#pragma unroll
            for (int dtp = 0; dtp < 4; dtp++)
                LDSM_X4(vb[2 * dtp][0], vb[2 * dtp][1],
                        vb[2 * dtp + 1][0], vb[2 * dtp + 1][1],
                        vbase + (uint32_t)(dtp * 16 * AST2 + ko) * 2);
#pragma unroll
            for (int dt = 0; dt < 8; dt++)
                mma_f16(acc[dt], a0, a1, a2, a3, vb[dt][0], vb[dt][1]);
        }

        __syncthreads();
        if (it + 2 < NKT) {
            const int kt2 = (it + 2) * 64;
            const __half* ks = Kb + (size_t)(kt2 + ld) * DK + lh;
            const uint32_t kd = base + (uint32_t)(A_K0 + (it & 1) * A_KB + ld * AST2 + lh) * 2;
            const __half* vs = Vb + (size_t)ld * SEQ + kt2 + lh;
            const uint32_t vd = base + (uint32_t)(A_V0 + (it & 1) * A_VB + ld * AST2 + lh) * 2;
            CP_ASYNC16(kd, ks); CP_ASYNC16(kd + 16, ks + 8);
            CP_ASYNC16(vd, vs); CP_ASYNC16(vd + 16, vs + 8);
        }
        CP_COMMIT();
    }

    // ---- epilogue: normalize, fp16 hi/lo split
    const int b = bh >> 4;
    const int h = bh & 15;
    const float inv0 = 1.0f / l_i[0];
    const float inv1 = 1.0f / l_i[1];
    const int r0 = q0 + wrow + G;
    const int r1 = r0 + 8;
    const size_t o0 = ((size_t)b * SEQ + r0) * DMODEL + h * DK;
    const size_t o1 = ((size_t)b * SEQ + r1) * DMODEL + h * DK;
#pragma unroll
    for (int dt = 0; dt < 8; dt++) {
        const int d = dt * 8 + 2 * T;
        float x0 = acc[dt][0] * inv0, y0 = acc[dt][1] * inv0;
        float x1 = acc[dt][2] * inv1, y1 = acc[dt][3] * inv1;
        __half2 h0, l0, h1, l1;
        __half hh, ll;
        f16_split(x0, hh, ll); h0.x = hh; l0.x = ll;
        f16_split(y0, hh, ll); h0.y = hh; l0.y = ll;
        f16_split(x1, hh, ll); h1.x = hh; l1.x = ll;
        f16_split(y1, hh, ll); h1.y = hh; l1.y = ll;
        *(__half2*)&Ohi[o0 + d] = h0;
        *(__half2*)&Olo[o0 + d] = l0;
        *(__half2*)&Ohi[o1 + d] = h1;
        *(__half2*)&Olo[o1 + d] = l1;
    }
}

// ---------------- launch ----------------
extern "C" void kernel_launch(void* const* d_in, const int* in_sizes, int n_in,
                              void* d_out, int out_size)
{
    const float* x  = (const float*)d_in[0];
    const float* Wq = (const float*)d_in[1];
    const float* bq = (const float*)d_in[2];
    const float* Wk = (const float*)d_in[3];
    const float* bk = (const float*)d_in[4];
    const float* Wv = (const float*)d_in[5];
    const float* bv = (const float*)d_in[6];
    const float* Wo = (const float*)d_in[7];
    const float* bo = (const float*)d_in[8];
    float* out = (float*)d_out;

    __half *gq, *gk, *gv, *gxh, *gxl, *gah, *gal, *wq, *wk, *wv, *wo;
    cudaGetSymbolAddress((void**)&gq,  g_q);
    cudaGetSymbolAddress((void**)&gk,  g_k);
    cudaGetSymbolAddress((void**)&gv,  g_v);
    cudaGetSymbolAddress((void**)&gxh, g_xh);
    cudaGetSymbolAddress((void**)&gxl, g_xl);
    cudaGetSymbolAddress((void**)&gah, g_aoh);
    cudaGetSymbolAddress((void**)&gal, g_aol);
    cudaGetSymbolAddress((void**)&wq,  g_wq);
    cudaGetSymbolAddress((void**)&wk,  g_wk);
    cudaGetSymbolAddress((void**)&wv,  g_wv);
    cudaGetSymbolAddress((void**)&wo,  g_wo);

    cudaFuncSetAttribute(gemm2_f16, cudaFuncAttributeMaxDynamicSharedMemorySize,
                         B_SMEM);
    cudaFuncSetAttribute(attn_mma, cudaFuncAttributeMaxDynamicSharedMemorySize,
                         A_SMEM);

    split_all_kernel<<<(NTASK + 255) / 256, 256>>>(
        x, Wq, Wk, Wv, Wo, gxh, gxl, wq, wk, wv, wo);

    dim3 gqkv(DMODEL / 128, MROWS / 128, 3);
    gemm2_f16<<<gqkv, 256, B_SMEM>>>(gxh, gxl,
                                     wq, bq, gq,
                                     wk, bk, gk,
                                     wv, bv, gv, 1, 2, 3);

    attn_mma<<<dim3(SEQ / 128, BATCH * NHEAD), 256, A_SMEM>>>(gq, gk, gv, gah, gal);

    dim3 go(DMODEL / 128, MROWS / 128, 1);
    gemm2_f16<<<go, 256, B_SMEM>>>(gah, gal,
                                   wo, bo, out,
                                   wo, bo, out,
                                   wo, bo, out, 0, 0, 0);
}